// round 14
// baseline (speedup 1.0000x reference)
#include <cuda_runtime.h>
#include <cstdint>
#include <math.h>

#define Bb   64
#define Tt   128
#define OUTT 64
#define Ee   256
#define Hh   512
#define H2v  1024
#define H3v  1536
#define H4v  2048
#define Vv   20000
#define SOSv 1

typedef unsigned long long u64;
typedef unsigned short u16;

// ---------------- scratch ----------------
__device__ float d_GinF[Tt * Bb * H4v];
__device__ float d_GinB[Tt * Bb * H4v];
__device__ float d_GinD[OUTT * Bb * H4v];
__device__ float d_enc[Tt * Bb * H2v];
__device__ float d_hf[2][Bb * Hh];
__device__ float d_hb[2][Bb * Hh];
__device__ float d_cf[Bb * Hh];
__device__ float d_cb[Bb * Hh];
__device__ float d_hd[2][Bb * Hh];
__device__ float d_cd[Bb * Hh];
__device__ float d_hcat[Bb * H2v];
__device__ float d_ccat[Bb * H2v];
__device__ float d_E[Tt * Bb * Hh];
__device__ float d_eb[Tt * Bb];
__device__ float d_WVt[Hh * H2v];
__device__ float d_zero[512];
__device__ u16  d_WfcH[(size_t)Vv * H3v];
__device__ u16  d_WfcL[(size_t)Vv * H3v];
__device__ u16  d_ctxH[OUTT * Bb * H3v];
__device__ u16  d_ctxL[OUTT * Bb * H3v];
__device__ int   d_tokF[Tt * Bb];
__device__ int   d_tokB[Tt * Bb];
__device__ int   d_tokD[OUTT * Bb];
__device__ unsigned d_bcE, d_bgE, d_bcE2, d_bgE2, d_bcD, d_bgD;

__device__ __forceinline__ float sigf(float x) { return 1.f / (1.f + expf(-x)); }

__device__ __forceinline__ u64 pack2(float lo, float hi) {
    u64 r; asm("mov.b64 %0, {%1, %2};" : "=l"(r) : "f"(lo), "f"(hi)); return r;
}
__device__ __forceinline__ void unpack2(u64 v, float& lo, float& hi) {
    unsigned int a, b;
    asm("mov.b64 {%0, %1}, %2;" : "=r"(a), "=r"(b) : "l"(v));
    lo = __uint_as_float(a); hi = __uint_as_float(b);
}
__device__ __forceinline__ u64 ffma2(u64 a, u64 b, u64 c) {
    u64 d; asm("fma.rn.f32x2 %0, %1, %2, %3;" : "=l"(d) : "l"(a), "l"(b), "l"(c)); return d;
}
__device__ __forceinline__ uint32_t smem_u32(const void* p) {
    uint32_t a;
    asm("{ .reg .u64 t; cvta.to.shared.u64 t, %1; cvt.u32.u64 %0, t; }" : "=r"(a) : "l"(p));
    return a;
}
__device__ __forceinline__ unsigned pbf2(float lo, float hi) {
    unsigned r; asm("cvt.rn.bf16x2.f32 %0, %1, %2;" : "=r"(r) : "f"(hi), "f"(lo)); return r;
}
__device__ __forceinline__ void ldsm4(uint32_t& r0, uint32_t& r1, uint32_t& r2, uint32_t& r3,
                                      uint32_t addr) {
    asm volatile("ldmatrix.sync.aligned.m8n8.x4.shared.b16 {%0,%1,%2,%3}, [%4];"
                 : "=r"(r0), "=r"(r1), "=r"(r2), "=r"(r3) : "r"(addr));
}
__device__ __forceinline__ void mma16816(float* c, const uint32_t* a, const uint32_t* b) {
    asm volatile("mma.sync.aligned.m16n8k16.row.col.f32.bf16.bf16.f32 "
                 "{%0,%1,%2,%3}, {%4,%5,%6,%7}, {%8,%9}, {%0,%1,%2,%3};"
                 : "+f"(c[0]), "+f"(c[1]), "+f"(c[2]), "+f"(c[3])
                 : "r"(a[0]), "r"(a[1]), "r"(a[2]), "r"(a[3]), "r"(b[0]), "r"(b[1]));
}
#define CPA16(dst, src) asm volatile("cp.async.cg.shared.global [%0], [%1], 16;" :: "r"(dst), "l"(src))
#define CPCOMMIT()      asm volatile("cp.async.commit_group;" ::: "memory")
#define CPWAIT(n)       asm volatile("cp.async.wait_group %0;" :: "n"(n) : "memory")

// ---------------- grid barrier (tight spin) ----------------
__device__ __forceinline__ void gridbar(unsigned* cnt, unsigned* gen, unsigned nb) {
    __syncthreads();
    if (threadIdx.x == 0) {
        __threadfence();
        volatile unsigned* vg = gen;
        unsigned g = *vg;
        if (atomicInc(cnt, nb - 1) == nb - 1) {
            *vg = g + 1;
        } else {
            while (*vg == g) { }
        }
    }
    __syncthreads();
}

#define MM_LDS   40
#define MM_REG   10240
#define MM_STAGE (4 * MM_REG)
#define MM_SMEM  (2 * MM_STAGE)
#define FC3_SMEM (3 * MM_STAGE)

// ======================= fp32-input HMMA split GEMM (gathers + E) ==============
template <bool GATHER>
__global__ void __launch_bounds__(256)
mma_gemm_kernel(const float* __restrict__ A, const int* __restrict__ gidx,
                const float* __restrict__ W, const float* __restrict__ bias,
                float* __restrict__ C, int Nn, int K) {
    extern __shared__ char smem[];
    const uint32_t sb = smem_u32(smem);
    const int tid = threadIdx.x, wid = tid >> 5, lane = tid & 31;
    const int warp_m = wid & 1, warp_n = wid >> 1;
    const int m0 = blockIdx.x * 128;
    const int n0 = blockIdx.y * 128;
    const int NKB = K / 32;

    float acc[4][4][4];
#pragma unroll
    for (int mt = 0; mt < 4; mt++)
#pragma unroll
        for (int nt = 0; nt < 4; nt++)
#pragma unroll
            for (int i = 0; i < 4; i++) acc[mt][nt][i] = 0.f;

    const int grow = tid >> 3, gkq = tid & 7;
    float4 ga[4], gb[4];

    auto gload = [&](int s) {
        const int k0 = s * 32;
#pragma unroll
        for (int r = 0; r < 4; r++) {
            int m = grow + r * 32;
            const float* ap = GATHER ? (A + (size_t)gidx[m0 + m] * K)
                                     : (A + (size_t)(m0 + m) * K);
            ga[r] = *(const float4*)(ap + k0 + gkq * 4);
            int gn = n0 + m;
            gb[r] = (gn < Nn) ? *(const float4*)(W + (size_t)gn * K + k0 + gkq * 4)
                              : make_float4(0.f, 0.f, 0.f, 0.f);
        }
    };
    auto cvst = [&](char* base, float4 v, int off) {
        unsigned bx = __float_as_uint(v.x), by = __float_as_uint(v.y);
        unsigned bz = __float_as_uint(v.z), bw = __float_as_uint(v.w);
        unsigned h0 = (bx >> 16) | (by & 0xFFFF0000u);
        unsigned h1 = (bz >> 16) | (bw & 0xFFFF0000u);
        float rx = v.x - __uint_as_float(bx & 0xFFFF0000u);
        float ry = v.y - __uint_as_float(by & 0xFFFF0000u);
        float rz = v.z - __uint_as_float(bz & 0xFFFF0000u);
        float rw = v.w - __uint_as_float(bw & 0xFFFF0000u);
        *(uint2*)(base + off)          = make_uint2(h0, h1);
        *(uint2*)(base + MM_REG + off) = make_uint2(pbf2(rx, ry), pbf2(rz, rw));
    };
    auto sstore = [&](int buf) {
        char* st = smem + buf * MM_STAGE;
#pragma unroll
        for (int r = 0; r < 4; r++) {
            int off = (grow + r * 32) * 80 + gkq * 8;
            cvst(st, ga[r], off);
            cvst(st + 2 * MM_REG, gb[r], off);
        }
    };

    gload(0); sstore(0); __syncthreads();

    for (int kb = 0; kb < NKB; kb++) {
        if (kb + 1 < NKB) gload(kb + 1);
        const uint32_t st = sb + (kb & 1) * MM_STAGE;
#pragma unroll
        for (int kh = 0; kh < 2; kh++) {
            const int kk = kh * 16;
            const uint32_t aoff = ((warp_m * 64 + (lane & 15)) * MM_LDS + kk + ((lane >> 4) << 3)) * 2;
            const uint32_t boff = ((warp_n * 32 + ((lane >> 4) << 3) + (lane & 7)) * MM_LDS
                                   + kk + (((lane >> 3) & 1) << 3)) * 2;
            uint32_t ah[4][4], bh[2][4], bl[2][4];
#pragma unroll
            for (int mt = 0; mt < 4; mt++)
                ldsm4(ah[mt][0], ah[mt][1], ah[mt][2], ah[mt][3],
                      st + aoff + mt * 16 * MM_LDS * 2);
#pragma unroll
            for (int p = 0; p < 2; p++) {
                ldsm4(bh[p][0], bh[p][1], bh[p][2], bh[p][3],
                      st + 2 * MM_REG + boff + p * 16 * MM_LDS * 2);
                ldsm4(bl[p][0], bl[p][1], bl[p][2], bl[p][3],
                      st + 3 * MM_REG + boff + p * 16 * MM_LDS * 2);
            }
#pragma unroll
            for (int mt = 0; mt < 4; mt++)
#pragma unroll
                for (int nt = 0; nt < 4; nt++) {
                    mma16816(acc[mt][nt], ah[mt], &bh[nt >> 1][(nt & 1) * 2]);
                    mma16816(acc[mt][nt], ah[mt], &bl[nt >> 1][(nt & 1) * 2]);
                }
            uint32_t al[4][4];
#pragma unroll
            for (int mt = 0; mt < 4; mt++)
                ldsm4(al[mt][0], al[mt][1], al[mt][2], al[mt][3],
                      st + MM_REG + aoff + mt * 16 * MM_LDS * 2);
#pragma unroll
            for (int mt = 0; mt < 4; mt++)
#pragma unroll
                for (int nt = 0; nt < 4; nt++)
                    mma16816(acc[mt][nt], al[mt], &bh[nt >> 1][(nt & 1) * 2]);
        }
        if (kb + 1 < NKB) sstore((kb + 1) & 1);
        __syncthreads();
    }

    const int g = lane >> 2, q = lane & 3;
#pragma unroll
    for (int mt = 0; mt < 4; mt++) {
        int row = m0 + warp_m * 64 + mt * 16 + g;
#pragma unroll
        for (int nt = 0; nt < 4; nt++) {
            int col = n0 + warp_n * 32 + nt * 8 + q * 2;
            if (col < Nn) {
                float b0 = bias[col], b1 = bias[col + 1];
                float* c0 = C + (size_t)row * Nn + col;
                float* c1 = C + (size_t)(row + 8) * Nn + col;
                c0[0] = acc[mt][nt][0] + b0; c0[1] = acc[mt][nt][1] + b1;
                c1[0] = acc[mt][nt][2] + b0; c1[1] = acc[mt][nt][3] + b1;
            }
        }
    }
}

// ======= FC: 3-stage cp.async, ONE sync per K-block, full registers =======
__global__ void __launch_bounds__(256)
fc3_kernel(const u16* __restrict__ AH, const u16* __restrict__ AL,
           const u16* __restrict__ WH, const u16* __restrict__ WL,
           const float* __restrict__ bias, float* __restrict__ C,
           int Nn, int K) {
    extern __shared__ char smem[];
    const uint32_t sb = smem_u32(smem);
    const int tid = threadIdx.x, wid = tid >> 5, lane = tid & 31;
    const int warp_m = wid & 1, warp_n = wid >> 1;
    const int m0 = blockIdx.x * 128;
    const int n0 = blockIdx.y * 128;
    const int NKB = K / 32;

    float acc[4][4][4];
#pragma unroll
    for (int mt = 0; mt < 4; mt++)
#pragma unroll
        for (int nt = 0; nt < 4; nt++)
#pragma unroll
            for (int i = 0; i < 4; i++) acc[mt][nt][i] = 0.f;

    const int lrow0 = tid >> 2, lkq0 = tid & 3;
    const int lrow1 = (tid + 256) >> 2;
    const int wrowc = (n0 + lrow0 < Nn) ? (n0 + lrow0) : (Nn - 1);
    const int wrowc1 = (n0 + lrow1 < Nn) ? (n0 + lrow1) : (Nn - 1);

    auto issue = [&](int s) {
        const uint32_t st = sb + (s % 3) * MM_STAGE;
        const int k0 = s * 32;
        uint32_t d0 = st + lrow0 * 80 + lkq0 * 16;
        uint32_t d1 = st + lrow1 * 80 + lkq0 * 16;
        size_t ao0 = (size_t)(m0 + lrow0) * K + k0 + lkq0 * 8;
        size_t ao1 = (size_t)(m0 + lrow1) * K + k0 + lkq0 * 8;
        size_t wo0 = (size_t)wrowc * K + k0 + lkq0 * 8;
        size_t wo1 = (size_t)wrowc1 * K + k0 + lkq0 * 8;
        CPA16(d0, AH + ao0);                 CPA16(d1, AH + ao1);
        CPA16(d0 + MM_REG, AL + ao0);        CPA16(d1 + MM_REG, AL + ao1);
        CPA16(d0 + 2 * MM_REG, WH + wo0);    CPA16(d1 + 2 * MM_REG, WH + wo1);
        CPA16(d0 + 3 * MM_REG, WL + wo0);    CPA16(d1 + 3 * MM_REG, WL + wo1);
        CPCOMMIT();
    };

    issue(0); issue(1);

    for (int kb = 0; kb < NKB; kb++) {
        if (kb + 1 < NKB) { CPWAIT(1); } else { CPWAIT(0); }
        __syncthreads();                 // slot kb%3 published; all warps past compute(kb-1)
        if (kb + 2 < NKB) issue(kb + 2); // slot (kb+2)%3 == (kb-1)%3: free by the sync above
        const uint32_t st = sb + (kb % 3) * MM_STAGE;
#pragma unroll
        for (int kh = 0; kh < 2; kh++) {
            const int kk = kh * 16;
            const uint32_t aoff = ((warp_m * 64 + (lane & 15)) * MM_LDS + kk + ((lane >> 4) << 3)) * 2;
            const uint32_t boff = ((warp_n * 32 + ((lane >> 4) << 3) + (lane & 7)) * MM_LDS
                                   + kk + (((lane >> 3) & 1) << 3)) * 2;
            uint32_t ah[4][4], bh[2][4], bl[2][4];
#pragma unroll
            for (int mt = 0; mt < 4; mt++)
                ldsm4(ah[mt][0], ah[mt][1], ah[mt][2], ah[mt][3],
                      st + aoff + mt * 16 * MM_LDS * 2);
#pragma unroll
            for (int p = 0; p < 2; p++) {
                ldsm4(bh[p][0], bh[p][1], bh[p][2], bh[p][3],
                      st + 2 * MM_REG + boff + p * 16 * MM_LDS * 2);
                ldsm4(bl[p][0], bl[p][1], bl[p][2], bl[p][3],
                      st + 3 * MM_REG + boff + p * 16 * MM_LDS * 2);
            }
#pragma unroll
            for (int mt = 0; mt < 4; mt++)
#pragma unroll
                for (int nt = 0; nt < 4; nt++) {
                    mma16816(acc[mt][nt], ah[mt], &bh[nt >> 1][(nt & 1) * 2]);
                    mma16816(acc[mt][nt], ah[mt], &bl[nt >> 1][(nt & 1) * 2]);
                }
            uint32_t al[4][4];
#pragma unroll
            for (int mt = 0; mt < 4; mt++)
                ldsm4(al[mt][0], al[mt][1], al[mt][2], al[mt][3],
                      st + MM_REG + aoff + mt * 16 * MM_LDS * 2);
#pragma unroll
            for (int mt = 0; mt < 4; mt++)
#pragma unroll
                for (int nt = 0; nt < 4; nt++)
                    mma16816(acc[mt][nt], al[mt], &bh[nt >> 1][(nt & 1) * 2]);
        }
    }

    const int g = lane >> 2, q = lane & 3;
#pragma unroll
    for (int mt = 0; mt < 4; mt++) {
        int row = m0 + warp_m * 64 + mt * 16 + g;
#pragma unroll
        for (int nt = 0; nt < 4; nt++) {
            int col = n0 + warp_n * 32 + nt * 8 + q * 2;
            if (col < Nn) {
                float b0 = bias[col], b1 = bias[col + 1];
                float* c0 = C + (size_t)row * Nn + col;
                float* c1 = C + (size_t)(row + 8) * Nn + col;
                c0[0] = acc[mt][nt][0] + b0; c0[1] = acc[mt][nt][1] + b1;
                c1[0] = acc[mt][nt][2] + b0; c1[1] = acc[mt][nt][3] + b1;
            }
        }
    }
}

// ---------------- prep ----------------
__global__ void ebias_kernel(const float* __restrict__ bV) {
    int m = blockIdx.x * 8 + (threadIdx.x >> 5);
    int lane = threadIdx.x & 31;
    const float4* er = (const float4*)(d_enc + (size_t)m * H2v);
    float s = 0.f;
#pragma unroll
    for (int it = 0; it < 8; it++) {
        float4 e4 = er[it * 32 + lane];
        float4 b4 = ((const float4*)bV)[it * 32 + lane];
        s += e4.x * b4.x + e4.y * b4.y + e4.z * b4.z + e4.w * b4.w;
    }
#pragma unroll
    for (int o = 16; o; o >>= 1) s += __shfl_xor_sync(0xffffffffu, s, o);
    if (lane == 0) d_eb[m] = s;
}

__global__ void init_prep_kernel(const int* __restrict__ x, const int* __restrict__ lens,
                                 const int* __restrict__ y, const float* __restrict__ WV) {
    int idx = blockIdx.x * blockDim.x + threadIdx.x;
    int stride = gridDim.x * blockDim.x;
    for (int i = idx; i < Tt * Bb * H2v; i += stride) d_enc[i] = 0.f;
    for (int i = idx; i < Bb * Hh; i += stride) {
        d_hf[0][i] = 0.f; d_hb[0][i] = 0.f; d_cf[i] = 0.f; d_cb[i] = 0.f;
    }
    for (int i = idx; i < 512; i += stride) d_zero[i] = 0.f;
    for (int i = idx; i < Hh * H2v; i += stride) {
        int h = i >> 10, j = i & 1023;
        d_WVt[i] = WV[j * Hh + h];
    }
    for (int i = idx; i < Tt * Bb; i += stride) {
        int t = i / Bb, b = i % Bb;
        d_tokF[i] = x[b * Tt + t];
        int p = lens[b] - 1 - t; if (p < 0) p = 0;
        d_tokB[i] = x[b * Tt + p];
    }
    for (int i = idx; i < OUTT * Bb; i += stride) {
        int t = i / Bb, b = i % Bb;
        d_tokD[i] = (t == 0) ? SOSv : y[b * OUTT + (t - 1)];
    }
}

// ---------------- small FFMA GEMM (h0/c0) ----------------
template <int BM, int BN, int BK, int TM, int TN>
__global__ void __launch_bounds__((BM / TM) * (BN / TN))
gemm_kernel(const float* __restrict__ A, int lda,
            const float* __restrict__ W, const float* __restrict__ bias,
            float* __restrict__ C, int M, int Nn, int K) {
    constexpr int NT = (BM / TM) * (BN / TN);
    __shared__ __align__(16) float As[BK][BM + 4];
    __shared__ __align__(16) float Bs[BK][BN + 4];
    const int tid = threadIdx.x;
    const int tx = tid % (BN / TN);
    const int ty = tid / (BN / TN);
    const int m0 = blockIdx.y * BM;
    const int n0 = blockIdx.x * BN;

    u64 acc2[TM][TN / 2];
#pragma unroll
    for (int i = 0; i < TM; i++)
#pragma unroll
        for (int j = 0; j < TN / 2; j++) acc2[i][j] = 0ULL;

    const int nK = K / BK;
    for (int kb = 0; kb < nK; kb++) {
        const int k0 = kb * BK;
#pragma unroll
        for (int l = 0; l < (BM * BK / 4) / NT; l++) {
            int i = tid + l * NT;
            int m = i / (BK / 4), kq = i % (BK / 4);
            float4 v = make_float4(0.f, 0.f, 0.f, 0.f);
            int gm = m0 + m;
            if (gm < M) v = *(const float4*)(A + (size_t)gm * lda + k0 + kq * 4);
            int kk = kq * 4;
            As[kk][m] = v.x; As[kk + 1][m] = v.y; As[kk + 2][m] = v.z; As[kk + 3][m] = v.w;
        }
#pragma unroll
        for (int l = 0; l < (BN * BK / 4) / NT; l++) {
            int i = tid + l * NT;
            int n = i / (BK / 4), kq = i % (BK / 4);
            float4 v = make_float4(0.f, 0.f, 0.f, 0.f);
            int gn = n0 + n;
            if (gn < Nn) v = *(const float4*)(W + (size_t)gn * K + k0 + kq * 4);
            int kk = kq * 4;
            Bs[kk][n] = v.x; Bs[kk + 1][n] = v.y; Bs[kk + 2][n] = v.z; Bs[kk + 3][n] = v.w;
        }
        __syncthreads();
#pragma unroll
        for (int k = 0; k < BK; k++) {
            float a[TM];
#pragma unroll
            for (int i = 0; i < TM; i += 4) {
                float4 v = *(const float4*)&As[k][ty * TM + i];
                a[i] = v.x; a[i + 1] = v.y; a[i + 2] = v.z; a[i + 3] = v.w;
            }
            u64 bb[TN / 2];
#pragma unroll
            for (int j = 0; j < TN; j += 4) {
                ulonglong2 v = *(const ulonglong2*)&Bs[k][tx * TN + j];
                bb[j / 2] = v.x; bb[j / 2 + 1] = v.y;
            }
#pragma unroll
            for (int i = 0; i < TM; i++) {
                u64 aa = pack2(a[i], a[i]);
#pragma unroll
                for (int j = 0; j < TN / 2; j++) acc2[i][j] = ffma2(aa, bb[j], acc2[i][j]);
            }
        }
        __syncthreads();
    }
#pragma unroll
    for (int i = 0; i < TM; i++) {
        int gm = m0 + ty * TM + i;
        if (gm >= M) continue;
        float* crow = C + (size_t)gm * Nn;
#pragma unroll
        for (int p = 0; p < TN / 2; p++) {
            float lo, hi; unpack2(acc2[i][p], lo, hi);
            int gn = n0 + tx * TN + 2 * p;
            if (gn < Nn)     crow[gn]     = lo + bias[gn];
            if (gn + 1 < Nn) crow[gn + 1] = hi + bias[gn + 1];
        }
    }
}

// ================= persistent encoder (blocks>=128 convert W_fc) =================
#define ENC_SMEM ((512 * 36 + 2 * 32 * 68 + 64 * 33) * 4)

__global__ void __launch_bounds__(256)
lstm_enc_persist(const float* __restrict__ Whf, const float* __restrict__ Whb,
                 const int* __restrict__ lens, const float* __restrict__ Wfc) {
    extern __shared__ float sm[];
    const int tid = threadIdx.x;
    const int bid = blockIdx.x;

    if (bid >= 128) {
        const int n4 = Vv * H3v / 4;
        for (int i = (bid - 128) * 256 + tid; i < n4; i += 20 * 256) {
            float4 v = ((const float4*)Wfc)[i];
            unsigned bx = __float_as_uint(v.x), by = __float_as_uint(v.y);
            unsigned bz = __float_as_uint(v.z), bw = __float_as_uint(v.w);
            unsigned h0 = (bx >> 16) | (by & 0xFFFF0000u);
            unsigned h1 = (bz >> 16) | (bw & 0xFFFF0000u);
            float rx = v.x - __uint_as_float(bx & 0xFFFF0000u);
            float ry = v.y - __uint_as_float(by & 0xFFFF0000u);
            float rz = v.z - __uint_as_float(bz & 0xFFFF0000u);
            float rw = v.w - __uint_as_float(bw & 0xFFFF0000u);
            ((uint2*)d_WfcH)[i] = make_uint2(h0, h1);
            ((uint2*)d_WfcL)[i] = make_uint2(pbf2(rx, ry), pbf2(rz, rw));
        }
        return;
    }

    float* Wt  = sm;
    float* Asb = sm + 512 * 36;
    float* gsm = Asb + 2 * 32 * 68;
    const int dir = bid >> 6;
    const int hb0 = (bid & 63) << 3;
    const float* Whh = dir ? Whb : Whf;
    float* cst = dir ? d_cb : d_cf;
    unsigned* bcnt = dir ? &d_bcE2 : &d_bcE;
    unsigned* bgen = dir ? &d_bgE2 : &d_bgE;

    for (int i = tid; i < 32 * 512; i += 256) {
        int n = i >> 9, k = i & 511;
        int grow = ((n >> 3) << 9) + hb0 + (n & 7);
        Wt[k * 36 + n] = Whh[(size_t)grow * 512 + k];
    }
    __syncthreads();

    const int tx = tid & 7, ty = tid >> 3;
    const int sm_m0 = tid >> 3, sm_kq0 = tid & 7;
    const int sm_m1 = (tid + 256) >> 3;

    int gidx8[8];
#pragma unroll
    for (int r = 0; r < 2; r++) {
        int p = tid + r * 256;
        int b = p >> 3, u = p & 7;
        gidx8[r * 4]     = b * H4v + hb0 + u;
        gidx8[r * 4 + 1] = b * H4v + 512 + hb0 + u;
        gidx8[r * 4 + 2] = b * H4v + 1024 + hb0 + u;
        gidx8[r * 4 + 3] = b * H4v + 1536 + hb0 + u;
    }

    auto stage_write = [&](float* A, float4 r0, float4 r1) {
        A[(sm_kq0 * 4 + 0) * 68 + sm_m0] = r0.x;
        A[(sm_kq0 * 4 + 1) * 68 + sm_m0] = r0.y;
        A[(sm_kq0 * 4 + 2) * 68 + sm_m0] = r0.z;
        A[(sm_kq0 * 4 + 3) * 68 + sm_m0] = r0.w;
        A[(sm_kq0 * 4 + 0) * 68 + sm_m1] = r1.x;
        A[(sm_kq0 * 4 + 1) * 68 + sm_m1] = r1.y;
        A[(sm_kq0 * 4 + 2) * 68 + sm_m1] = r1.z;
        A[(sm_kq0 * 4 + 3) * 68 + sm_m1] = r1.w;
    };

    for (int t = 0; t < Tt; t++) {
        const int cur = t & 1;
        const float* hprev = dir ? d_hb[cur] : d_hf[cur];
        float* hnext       = dir ? d_hb[cur ^ 1] : d_hf[cur ^ 1];
        const float* Gin = (dir ? d_GinB : d_GinF) + (size_t)t * Bb * H4v;

        float ginr[8];
#pragma unroll
        for (int r = 0; r < 8; r++) ginr[r] = __ldg(Gin + gidx8[r]);

        u64 acc[2][2] = {{0ULL, 0ULL}, {0ULL, 0ULL}};
        float4 r0 = *(const float4*)(hprev + sm_m0 * 512 + sm_kq0 * 4);
        float4 r1 = *(const float4*)(hprev + sm_m1 * 512 + sm_kq0 * 4);
        stage_write(Asb, r0, r1);
        __syncthreads();

        for (int kb = 0; kb < 16; kb++) {
            if (kb + 1 < 16) {
                int k0 = (kb + 1) * 32;
                r0 = *(const float4*)(hprev + sm_m0 * 512 + k0 + sm_kq0 * 4);
                r1 = *(const float4*)(hprev + sm_m1 * 512 + k0 + sm_kq0 * 4);
            }
            const float* A = Asb + (kb & 1) * 2176;
#pragma unroll
            for (int k = 0; k < 32; k++) {
                float2 a = *(const float2*)(A + k * 68 + ty * 2);
                ulonglong2 w = *(const ulonglong2*)(Wt + (kb * 32 + k) * 36 + tx * 4);
                u64 p0 = pack2(a.x, a.x), p1 = pack2(a.y, a.y);
                acc[0][0] = ffma2(p0, w.x, acc[0][0]);
                acc[0][1] = ffma2(p0, w.y, acc[0][1]);
                acc[1][0] = ffma2(p1, w.x, acc[1][0]);
                acc[1][1] = ffma2(p1, w.y, acc[1][1]);
            }
            if (kb + 1 < 16) stage_write(Asb + ((kb + 1) & 1) * 2176, r0, r1);
            __syncthreads();
        }
#pragma unroll
        for (int i = 0; i < 2; i++) {
            int m = ty * 2 + i;
#pragma unroll
            for (int p = 0; p < 2; p++) {
                float lo, hi; unpack2(acc[i][p], lo, hi);
                int j0 = tx * 4 + 2 * p;
                gsm[m * 33 + j0]     = lo;
                gsm[m * 33 + j0 + 1] = hi;
            }
        }
        __syncthreads();
#pragma unroll
        for (int r = 0; r < 2; r++) {
            int p = tid + r * 256;
            int b = p >> 3, u = p & 7;
            float gi = gsm[b * 33 + u]      + ginr[r * 4];
            float gf = gsm[b * 33 + 8 + u]  + ginr[r * 4 + 1];
            float gg = gsm[b * 33 + 16 + u] + ginr[r * 4 + 2];
            float go = gsm[b * 33 + 24 + u] + ginr[r * 4 + 3];
            int hidx = b * Hh + hb0 + u;
            bool msk = t < lens[b];
            float c_old = cst[hidx];
            float c2 = sigf(gf) * c_old + sigf(gi) * tanhf(gg);
            float h2 = sigf(go) * tanhf(c2);
            hnext[hidx] = msk ? h2 : hprev[hidx];
            if (msk) {
                cst[hidx] = c2;
                if (dir == 0) d_enc[((size_t)t * Bb + b) * H2v + hb0 + u] = h2;
                else {
                    int tout = lens[b] - 1 - t;
                    d_enc[((size_t)tout * Bb + b) * H2v + Hh + hb0 + u] = h2;
                }
            }
        }
        gridbar(bcnt, bgen, 64);
    }
}

// ================= persistent decoder (writes ctxH/ctxL split directly) =========
#define DEC_SMEM ((512 * 20 + 2 * 32 * 68 + 64 * 17 + 512 + 128 + 128) * 4)

__global__ void __launch_bounds__(256)
lstm_dec_persist(const float* __restrict__ Whd) {
    extern __shared__ float sm[];
    float* WtD = sm;
    float* Asb = WtD + 512 * 20;
    float* gsm = Asb + 2 * 32 * 68;
    float* qs  = gsm + 64 * 17;
    float* es  = qs + 512;
    float* as_ = es + 128;
    const int tid = threadIdx.x;
    const int bid = blockIdx.x;
    const int hb0 = bid << 2;
    const int ab  = bid & 63;
    const int half = bid >> 6;

    for (int i = tid; i < 16 * 512; i += 256) {
        int n = i >> 9, k = i & 511;
        int grow = ((n >> 2) << 9) + hb0 + (n & 3);
        WtD[k * 20 + n] = Whd[(size_t)grow * 512 + k];
    }
    __syncthreads();

    const int tx = tid & 7, ty = tid >> 3;
    const int sm_m0 = tid >> 3, sm_kq0 = tid & 7;
    const int sm_m1 = (tid + 256) >> 3;

    int gidx4[4];
    {
        int b = tid >> 2, u = tid & 3;
        gidx4[0] = b * H4v + hb0 + u;
        gidx4[1] = b * H4v + 512 + hb0 + u;
        gidx4[2] = b * H4v + 1024 + hb0 + u;
        gidx4[3] = b * H4v + 1536 + hb0 + u;
    }

    auto stage_write = [&](float* A, float4 r0, float4 r1) {
        A[(sm_kq0 * 4 + 0) * 68 + sm_m0] = r0.x;
        A[(sm_kq0 * 4 + 1) * 68 + sm_m0] = r0.y;
        A[(sm_kq0 * 4 + 2) * 68 + sm_m0] = r0.z;
        A[(sm_kq0 * 4 + 3) * 68 + sm_m0] = r0.w;
        A[(sm_kq0 * 4 + 0) * 68 + sm_m1] = r1.x;
        A[(sm_kq0 * 4 + 1) * 68 + sm_m1] = r1.y;
        A[(sm_kq0 * 4 + 2) * 68 + sm_m1] = r1.z;
        A[(sm_kq0 * 4 + 3) * 68 + sm_m1] = r1.w;
    };

    for (int t = 0; t < OUTT; t++) {
        const int cur = t & 1;
        const float* hprev = d_hd[cur];
        float* hnext       = d_hd[cur ^ 1];
        const float* Gin = d_GinD + (size_t)t * Bb * H4v;

        float ginr[4];
#pragma unroll
        for (int r = 0; r < 4; r++) ginr[r] = __ldg(Gin + gidx4[r]);

        u64 acc[2] = {0ULL, 0ULL};
        float4 r0 = *(const float4*)(hprev + sm_m0 * 512 + sm_kq0 * 4);
        float4 r1 = *(const float4*)(hprev + sm_m1 * 512 + sm_kq0 * 4);
        stage_write(Asb, r0, r1);
        __syncthreads();

        for (int kb = 0; kb < 16; kb++) {
            if (kb + 1 < 16) {
                int k0 = (kb + 1) * 32;
                r0 = *(const float4*)(hprev + sm_m0 * 512 + k0 + sm_kq0 * 4);
                r1 = *(const float4*)(hprev + sm_m1 * 512 + k0 + sm_kq0 * 4);
            }
            const float* A = Asb + (kb & 1) * 2176;
#pragma unroll
            for (int k = 0; k < 32; k++) {
                float2 a = *(const float2*)(A + k * 68 + ty * 2);
                u64 w = *(const u64*)(WtD + (kb * 32 + k) * 20 + tx * 2);
                acc[0] = ffma2(pack2(a.x, a.x), w, acc[0]);
                acc[1] = ffma2(pack2(a.y, a.y), w, acc[1]);
            }
            if (kb + 1 < 16) stage_write(Asb + ((kb + 1) & 1) * 2176, r0, r1);
            __syncthreads();
        }
#pragma unroll
        for (int i = 0; i < 2; i++) {
            int m = ty * 2 + i;
            float lo, hi; unpack2(acc[i], lo, hi);
            int n0 = tx * 2;
            gsm[m * 17 + n0]     = lo;
            gsm[m * 17 + n0 + 1] = hi;
        }
        __syncthreads();
        {
            int b = tid >> 2, u = tid & 3;
            float gi = gsm[b * 17 + u]      + ginr[0];
            float gf = gsm[b * 17 + 4 + u]  + ginr[1];
            float gg = gsm[b * 17 + 8 + u]  + ginr[2];
            float go = gsm[b * 17 + 12 + u] + ginr[3];
            int hidx = b * Hh + hb0 + u;
            float c_old = d_cd[hidx];
            float c2 = sigf(gf) * c_old + sigf(gi) * tanhf(gg);
            float h2 = sigf(go) * tanhf(c2);
            hnext[hidx] = h2;
            d_cd[hidx] = c2;
            size_t cidx = ((size_t)t * Bb + b) * H3v + H2v + hb0 + u;
            unsigned bits = __float_as_uint(h2);
            float rr = h2 - __uint_as_float(bits & 0xFFFF0000u);
            d_ctxH[cidx] = (u16)(bits >> 16);
            d_ctxL[cidx] = (u16)(pbf2(rr, rr) & 0xFFFFu);
        }
        gridbar(&d_bcD, &d_bgD, 128);

        const float* h2p = d_hd[cur ^ 1];
        if (tid < 128) ((float4*)qs)[tid] = ((const float4*)(h2p + (size_t)ab * Hh))[tid];
        __syncthreads();
        {
            int w = tid >> 5, lane = tid & 31;
#pragma unroll
            for (int i = 0; i < 16; i++) {
                int tt = w + 8 * i;
                const float4* Ep = (const float4*)(d_E + ((size_t)tt * Bb + ab) * Hh);
                float s = 0.f;
#pragma unroll
                for (int it = 0; it < 4; it++) {
                    int h4 = it * 32 + lane;
                    float4 e4 = Ep[h4];
                    float4 q4 = ((const float4*)qs)[h4];
                    s += e4.x * q4.x + e4.y * q4.y + e4.z * q4.z + e4.w * q4.w;
                }
#pragma unroll
                for (int o = 16; o; o >>= 1) s += __shfl_xor_sync(0xffffffffu, s, o);
                if (lane == 0) es[tt] = s + d_eb[tt * Bb + ab];
            }
        }
        __syncthreads();
        float mx = -1e30f;
        for (int i = 0; i < Tt; i++) mx = fmaxf(mx, es[i]);
        if (tid < Tt) as_[tid] = expf(es[tid] - mx);
        __syncthreads();
        float sum = 0.f;
        for (int i = 0; i < Tt; i++) sum += as_[i];
        float inv = 1.f / sum;
        if (tid < 128) {
            int idx4 = half * 128 + tid;
            float4 a4 = make_float4(0.f, 0.f, 0.f, 0.f);
            for (int tt = 0; tt < Tt; tt++) {
                int L = ab * Tt + tt;
                int t0 = L >> 6, b0 = L & 63;
                float4 e4 = ((const float4*)(d_enc + ((size_t)t0 * Bb + b0) * H2v))[idx4];
                float a = as_[tt];
                a4.x += a * e4.x; a4.y += a * e4.y; a4.z += a * e4.z; a4.w += a * e4.w;
            }
            a4.x *= inv; a4.y *= inv; a4.z *= inv; a4.w *= inv;
            size_t base = ((size_t)t * Bb + ab) * H3v + (size_t)idx4 * 4;
            unsigned b0_ = __float_as_uint(a4.x), b1_ = __float_as_uint(a4.y);
            unsigned b2_ = __float_as_uint(a4.z), b3_ = __float_as_uint(a4.w);
            unsigned h01 = (b0_ >> 16) | (b1_ & 0xFFFF0000u);
            unsigned h23 = (b2_ >> 16) | (b3_ & 0xFFFF0000u);
            float r0_ = a4.x - __uint_as_float(b0_ & 0xFFFF0000u);
            float r1_ = a4.y - __uint_as_float(b1_ & 0xFFFF0000u);
            float r2_ = a4.z - __uint_as_float(b2_ & 0xFFFF0000u);
            float r3_ = a4.w - __uint_as_float(b3_ & 0xFFFF0000u);
            *(uint2*)(d_ctxH + base) = make_uint2(h01, h23);
            *(uint2*)(d_ctxL + base) = make_uint2(pbf2(r0_, r1_), pbf2(r2_, r3_));
        }
        __syncthreads();
    }
}

// ---------------- concat final encoder states ----------------
__global__ void concat_hc() {
    int i = blockIdx.x * blockDim.x + threadIdx.x;
    if (i < Bb * H2v) {
        int b = i >> 10, h = i & 1023;
        d_hcat[i] = (h < Hh) ? d_hf[0][b * Hh + h] : d_hb[0][b * Hh + h - Hh];
        d_ccat[i] = (h < Hh) ? d_cf[b * Hh + h] : d_cb[b * Hh + h - Hh];
    }
}

// ---------------- host ----------------
static void* symaddr(const void* sym) {
    void* p = nullptr;
    cudaGetSymbolAddress(&p, sym);
    return p;
}

extern "C" void kernel_launch(void* const* d_in, const int* in_sizes, int n_in,
                              void* d_out, int out_size) {
    int s = (in_sizes[3] == 1) ? 4 : 3;
    const int*   x      = (const int*)d_in[0];
    const int*   lens   = (const int*)d_in[1];
    const int*   y      = (const int*)d_in[2];
    const float* emb_in = (const float*)d_in[s + 0];
    const float* emb_out= (const float*)d_in[s + 1];
    const float* W_ih_f = (const float*)d_in[s + 2];
    const float* W_hh_f = (const float*)d_in[s + 3];
    const float* b_f    = (const float*)d_in[s + 4];
    const float* W_ih_b = (const float*)d_in[s + 5];
    const float* W_hh_b = (const float*)d_in[s + 6];
    const float* b_b    = (const float*)d_in[s + 7];
    const float* W_rh   = (const float*)d_in[s + 8];
    const float* b_rh   = (const float*)d_in[s + 9];
    const float* W_rc   = (const float*)d_in[s + 10];
    const float* b_rc   = (const float*)d_in[s + 11];
    const float* W_ih_d = (const float*)d_in[s + 12];
    const float* W_hh_d = (const float*)d_in[s + 13];
    const float* b_d    = (const float*)d_in[s + 14];
    const float* W_V    = (const float*)d_in[s + 15];
    const float* b_V    = (const float*)d_in[s + 16];
    const float* W_fc   = (const float*)d_in[s + 17];
    const float* b_fc   = (const float*)d_in[s + 18];
    float* out = (float*)d_out;

    float* ginF = (float*)symaddr(d_GinF);
    float* ginB = (float*)symaddr(d_GinB);
    float* ginD = (float*)symaddr(d_GinD);
    float* hcat = (float*)symaddr(d_hcat);
    float* ccat = (float*)symaddr(d_ccat);
    float* hd   = (float*)symaddr(d_hd);
    float* cd   = (float*)symaddr(d_cd);
    float* enc  = (float*)symaddr(d_enc);
    float* Ebuf = (float*)symaddr(d_E);
    float* WVt  = (float*)symaddr(d_WVt);
    float* zer  = (float*)symaddr(d_zero);
    u16* WfcH = (u16*)symaddr(d_WfcH);
    u16* WfcL = (u16*)symaddr(d_WfcL);
    u16* ctxH = (u16*)symaddr(d_ctxH);
    u16* ctxL = (u16*)symaddr(d_ctxL);
    int* tokF = (int*)symaddr(d_tokF);
    int* tokB = (int*)symaddr(d_tokB);
    int* tokD = (int*)symaddr(d_tokD);

    static int attr_set = 0;
    if (!attr_set) {
        cudaFuncSetAttribute(mma_gemm_kernel<true>,
                             cudaFuncAttributeMaxDynamicSharedMemorySize, MM_SMEM);
        cudaFuncSetAttribute(mma_gemm_kernel<false>,
                             cudaFuncAttributeMaxDynamicSharedMemorySize, MM_SMEM);
        cudaFuncSetAttribute(fc3_kernel,
                             cudaFuncAttributeMaxDynamicSharedMemorySize, FC3_SMEM);
        cudaFuncSetAttribute(lstm_enc_persist,
                             cudaFuncAttributeMaxDynamicSharedMemorySize, ENC_SMEM);
        cudaFuncSetAttribute(lstm_dec_persist,
                             cudaFuncAttributeMaxDynamicSharedMemorySize, DEC_SMEM);
        attr_set = 1;
    }

    init_prep_kernel<<<512, 256>>>(x, lens, y, W_V);

    mma_gemm_kernel<true><<<dim3(Tt * Bb / 128, H4v / 128), 256, MM_SMEM>>>(
        emb_in, tokF, W_ih_f, b_f, ginF, H4v, Ee);
    mma_gemm_kernel<true><<<dim3(Tt * Bb / 128, H4v / 128), 256, MM_SMEM>>>(
        emb_in, tokB, W_ih_b, b_b, ginB, H4v, Ee);
    mma_gemm_kernel<true><<<dim3(OUTT * Bb / 128, H4v / 128), 256, MM_SMEM>>>(
        emb_out, tokD, W_ih_d, b_d, ginD, H4v, Ee);

    // encoder: 128 LSTM blocks + 20 spare blocks converting W_fc concurrently
    lstm_enc_persist<<<148, 256, ENC_SMEM>>>(W_hh_f, W_hh_b, lens, W_fc);

    concat_hc<<<(Bb * H2v + 255) / 256, 256>>>();
    gemm_kernel<64, 32, 16, 4, 4><<<dim3(Hh / 32, 1), 128>>>(
        hcat, H2v, W_rh, b_rh, hd, Bb, Hh, H2v);
    gemm_kernel<64, 32, 16, 4, 4><<<dim3(Hh / 32, 1), 128>>>(
        ccat, H2v, W_rc, b_rc, cd, Bb, Hh, H2v);

    mma_gemm_kernel<false><<<dim3(Tt * Bb / 128, Hh / 128), 256, MM_SMEM>>>(
        enc, nullptr, WVt, zer, Ebuf, Hh, H2v);
    ebias_kernel<<<Tt * Bb / 8, 256>>>(b_V);

    lstm_dec_persist<<<128, 256, DEC_SMEM>>>(W_hh_d);

    fc3_kernel<<<dim3(OUTT * Bb / 128, (Vv + 127) / 128), 256, FC3_SMEM>>>(
        ctxH, ctxL, WfcH, WfcL, b_fc, out, Vv, H3v);
}

// round 15
// speedup vs baseline: 1.0592x; 1.0592x over previous
#include <cuda_runtime.h>
#include <cstdint>
#include <math.h>

#define Bb   64
#define Tt   128
#define OUTT 64
#define Ee   256
#define Hh   512
#define H2v  1024
#define H3v  1536
#define H4v  2048
#define Vv   20000
#define SOSv 1

typedef unsigned long long u64;
typedef unsigned short u16;

// ---------------- scratch ----------------
__device__ float d_GinF[Tt * Bb * H4v];
__device__ float d_GinB[Tt * Bb * H4v];
__device__ float d_GinD[OUTT * Bb * H4v];
__device__ float d_enc[Tt * Bb * H2v];
__device__ float d_hf[2][Bb * Hh];
__device__ float d_hb[2][Bb * Hh];
__device__ float d_cf[Bb * Hh];
__device__ float d_cb[Bb * Hh];
__device__ float d_hd[2][Bb * Hh];
__device__ float d_cd[Bb * Hh];
__device__ float d_hcat[Bb * H2v];
__device__ float d_ccat[Bb * H2v];
__device__ float d_E[Tt * Bb * Hh];
__device__ float d_eb[Tt * Bb];
__device__ float d_WVt[Hh * H2v];
__device__ float d_zero[512];
__device__ u16  d_WfcH[(size_t)Vv * H3v];
__device__ u16  d_WfcL[(size_t)Vv * H3v];
__device__ u16  d_ctxH[OUTT * Bb * H3v];
__device__ u16  d_ctxL[OUTT * Bb * H3v];
__device__ int   d_tokF[Tt * Bb];
__device__ int   d_tokB[Tt * Bb];
__device__ int   d_tokD[OUTT * Bb];
__device__ unsigned d_bcE, d_bgE, d_bcE2, d_bgE2, d_bcD, d_bgD;

__device__ __forceinline__ float sigf(float x) { return 1.f / (1.f + expf(-x)); }

__device__ __forceinline__ u64 pack2(float lo, float hi) {
    u64 r; asm("mov.b64 %0, {%1, %2};" : "=l"(r) : "f"(lo), "f"(hi)); return r;
}
__device__ __forceinline__ void unpack2(u64 v, float& lo, float& hi) {
    unsigned int a, b;
    asm("mov.b64 {%0, %1}, %2;" : "=r"(a), "=r"(b) : "l"(v));
    lo = __uint_as_float(a); hi = __uint_as_float(b);
}
__device__ __forceinline__ u64 ffma2(u64 a, u64 b, u64 c) {
    u64 d; asm("fma.rn.f32x2 %0, %1, %2, %3;" : "=l"(d) : "l"(a), "l"(b), "l"(c)); return d;
}
__device__ __forceinline__ uint32_t smem_u32(const void* p) {
    uint32_t a;
    asm("{ .reg .u64 t; cvta.to.shared.u64 t, %1; cvt.u32.u64 %0, t; }" : "=r"(a) : "l"(p));
    return a;
}
__device__ __forceinline__ unsigned pbf2(float lo, float hi) {
    unsigned r; asm("cvt.rn.bf16x2.f32 %0, %1, %2;" : "=r"(r) : "f"(hi), "f"(lo)); return r;
}
__device__ __forceinline__ void ldsm4(uint32_t& r0, uint32_t& r1, uint32_t& r2, uint32_t& r3,
                                      uint32_t addr) {
    asm volatile("ldmatrix.sync.aligned.m8n8.x4.shared.b16 {%0,%1,%2,%3}, [%4];"
                 : "=r"(r0), "=r"(r1), "=r"(r2), "=r"(r3) : "r"(addr));
}
__device__ __forceinline__ void mma16816(float* c, const uint32_t* a, const uint32_t* b) {
    asm volatile("mma.sync.aligned.m16n8k16.row.col.f32.bf16.bf16.f32 "
                 "{%0,%1,%2,%3}, {%4,%5,%6,%7}, {%8,%9}, {%0,%1,%2,%3};"
                 : "+f"(c[0]), "+f"(c[1]), "+f"(c[2]), "+f"(c[3])
                 : "r"(a[0]), "r"(a[1]), "r"(a[2]), "r"(a[3]), "r"(b[0]), "r"(b[1]));
}
#define CPA16(dst, src) asm volatile("cp.async.cg.shared.global [%0], [%1], 16;" :: "r"(dst), "l"(src))
#define CPCOMMIT()      asm volatile("cp.async.commit_group;" ::: "memory")
#define CPWAIT(n)       asm volatile("cp.async.wait_group %0;" :: "n"(n) : "memory")

// ---------------- grid barrier (tight spin) ----------------
__device__ __forceinline__ void gridbar(unsigned* cnt, unsigned* gen, unsigned nb) {
    __syncthreads();
    if (threadIdx.x == 0) {
        __threadfence();
        volatile unsigned* vg = gen;
        unsigned g = *vg;
        if (atomicInc(cnt, nb - 1) == nb - 1) {
            *vg = g + 1;
        } else {
            while (*vg == g) { }
        }
    }
    __syncthreads();
}

#define MM_LDS   40
#define MM_REG   10240
#define MM_STAGE (4 * MM_REG)
#define MM_SMEM  (2 * MM_STAGE)

// ======================= fp32-input HMMA split GEMM (gathers + E) ==============
template <bool GATHER>
__global__ void __launch_bounds__(256)
mma_gemm_kernel(const float* __restrict__ A, const int* __restrict__ gidx,
                const float* __restrict__ W, const float* __restrict__ bias,
                float* __restrict__ C, int Nn, int K) {
    extern __shared__ char smem[];
    const uint32_t sb = smem_u32(smem);
    const int tid = threadIdx.x, wid = tid >> 5, lane = tid & 31;
    const int warp_m = wid & 1, warp_n = wid >> 1;
    const int m0 = blockIdx.x * 128;
    const int n0 = blockIdx.y * 128;
    const int NKB = K / 32;

    float acc[4][4][4];
#pragma unroll
    for (int mt = 0; mt < 4; mt++)
#pragma unroll
        for (int nt = 0; nt < 4; nt++)
#pragma unroll
            for (int i = 0; i < 4; i++) acc[mt][nt][i] = 0.f;

    const int grow = tid >> 3, gkq = tid & 7;
    float4 ga[4], gb[4];

    auto gload = [&](int s) {
        const int k0 = s * 32;
#pragma unroll
        for (int r = 0; r < 4; r++) {
            int m = grow + r * 32;
            const float* ap = GATHER ? (A + (size_t)gidx[m0 + m] * K)
                                     : (A + (size_t)(m0 + m) * K);
            ga[r] = *(const float4*)(ap + k0 + gkq * 4);
            int gn = n0 + m;
            gb[r] = (gn < Nn) ? *(const float4*)(W + (size_t)gn * K + k0 + gkq * 4)
                              : make_float4(0.f, 0.f, 0.f, 0.f);
        }
    };
    auto cvst = [&](char* base, float4 v, int off) {
        unsigned bx = __float_as_uint(v.x), by = __float_as_uint(v.y);
        unsigned bz = __float_as_uint(v.z), bw = __float_as_uint(v.w);
        unsigned h0 = (bx >> 16) | (by & 0xFFFF0000u);
        unsigned h1 = (bz >> 16) | (bw & 0xFFFF0000u);
        float rx = v.x - __uint_as_float(bx & 0xFFFF0000u);
        float ry = v.y - __uint_as_float(by & 0xFFFF0000u);
        float rz = v.z - __uint_as_float(bz & 0xFFFF0000u);
        float rw = v.w - __uint_as_float(bw & 0xFFFF0000u);
        *(uint2*)(base + off)          = make_uint2(h0, h1);
        *(uint2*)(base + MM_REG + off) = make_uint2(pbf2(rx, ry), pbf2(rz, rw));
    };
    auto sstore = [&](int buf) {
        char* st = smem + buf * MM_STAGE;
#pragma unroll
        for (int r = 0; r < 4; r++) {
            int off = (grow + r * 32) * 80 + gkq * 8;
            cvst(st, ga[r], off);
            cvst(st + 2 * MM_REG, gb[r], off);
        }
    };

    gload(0); sstore(0); __syncthreads();

    for (int kb = 0; kb < NKB; kb++) {
        if (kb + 1 < NKB) gload(kb + 1);
        const uint32_t st = sb + (kb & 1) * MM_STAGE;
#pragma unroll
        for (int kh = 0; kh < 2; kh++) {
            const int kk = kh * 16;
            const uint32_t aoff = ((warp_m * 64 + (lane & 15)) * MM_LDS + kk + ((lane >> 4) << 3)) * 2;
            const uint32_t boff = ((warp_n * 32 + ((lane >> 4) << 3) + (lane & 7)) * MM_LDS
                                   + kk + (((lane >> 3) & 1) << 3)) * 2;
            uint32_t ah[4][4], bh[2][4], bl[2][4];
#pragma unroll
            for (int mt = 0; mt < 4; mt++)
                ldsm4(ah[mt][0], ah[mt][1], ah[mt][2], ah[mt][3],
                      st + aoff + mt * 16 * MM_LDS * 2);
#pragma unroll
            for (int p = 0; p < 2; p++) {
                ldsm4(bh[p][0], bh[p][1], bh[p][2], bh[p][3],
                      st + 2 * MM_REG + boff + p * 16 * MM_LDS * 2);
                ldsm4(bl[p][0], bl[p][1], bl[p][2], bl[p][3],
                      st + 3 * MM_REG + boff + p * 16 * MM_LDS * 2);
            }
#pragma unroll
            for (int mt = 0; mt < 4; mt++)
#pragma unroll
                for (int nt = 0; nt < 4; nt++) {
                    mma16816(acc[mt][nt], ah[mt], &bh[nt >> 1][(nt & 1) * 2]);
                    mma16816(acc[mt][nt], ah[mt], &bl[nt >> 1][(nt & 1) * 2]);
                }
            uint32_t al[4][4];
#pragma unroll
            for (int mt = 0; mt < 4; mt++)
                ldsm4(al[mt][0], al[mt][1], al[mt][2], al[mt][3],
                      st + MM_REG + aoff + mt * 16 * MM_LDS * 2);
#pragma unroll
            for (int mt = 0; mt < 4; mt++)
#pragma unroll
                for (int nt = 0; nt < 4; nt++)
                    mma16816(acc[mt][nt], al[mt], &bh[nt >> 1][(nt & 1) * 2]);
        }
        if (kb + 1 < NKB) sstore((kb + 1) & 1);
        __syncthreads();
    }

    const int g = lane >> 2, q = lane & 3;
#pragma unroll
    for (int mt = 0; mt < 4; mt++) {
        int row = m0 + warp_m * 64 + mt * 16 + g;
#pragma unroll
        for (int nt = 0; nt < 4; nt++) {
            int col = n0 + warp_n * 32 + nt * 8 + q * 2;
            if (col < Nn) {
                float b0 = bias[col], b1 = bias[col + 1];
                float* c0 = C + (size_t)row * Nn + col;
                float* c1 = C + (size_t)(row + 8) * Nn + col;
                c0[0] = acc[mt][nt][0] + b0; c0[1] = acc[mt][nt][1] + b1;
                c1[0] = acc[mt][nt][2] + b0; c1[1] = acc[mt][nt][3] + b1;
            }
        }
    }
}

// ======= FC: bf16-preconverted, 2 CTAs/SM, ONE sync per K-block =======
__global__ void __launch_bounds__(256, 2)
fc_bf16_kernel(const u16* __restrict__ AH, const u16* __restrict__ AL,
               const u16* __restrict__ WH, const u16* __restrict__ WL,
               const float* __restrict__ bias, float* __restrict__ C,
               int Nn, int K) {
    extern __shared__ char smem[];
    const uint32_t sb = smem_u32(smem);
    const int tid = threadIdx.x, wid = tid >> 5, lane = tid & 31;
    const int warp_m = wid & 1, warp_n = wid >> 1;
    const int m0 = blockIdx.x * 128;
    const int n0 = blockIdx.y * 128;
    const int NKB = K / 32;

    float acc[4][4][4];
#pragma unroll
    for (int mt = 0; mt < 4; mt++)
#pragma unroll
        for (int nt = 0; nt < 4; nt++)
#pragma unroll
            for (int i = 0; i < 4; i++) acc[mt][nt][i] = 0.f;

    const int lrow0 = tid >> 2, lkq0 = tid & 3;
    const int lrow1 = (tid + 256) >> 2;
    const int wrowc = (n0 + lrow0 < Nn) ? (n0 + lrow0) : (Nn - 1);
    const int wrowc1 = (n0 + lrow1 < Nn) ? (n0 + lrow1) : (Nn - 1);

    auto issue = [&](int s) {
        const int buf = s & 1;
        const int k0 = s * 32;
        const uint32_t st = sb + buf * MM_STAGE;
        uint32_t d0 = st + lrow0 * 80 + lkq0 * 16;
        uint32_t d1 = st + lrow1 * 80 + lkq0 * 16;
        size_t ao0 = (size_t)(m0 + lrow0) * K + k0 + lkq0 * 8;
        size_t ao1 = (size_t)(m0 + lrow1) * K + k0 + lkq0 * 8;
        size_t wo0 = (size_t)wrowc * K + k0 + lkq0 * 8;
        size_t wo1 = (size_t)wrowc1 * K + k0 + lkq0 * 8;
        CPA16(d0, AH + ao0);                 CPA16(d1, AH + ao1);
        CPA16(d0 + MM_REG, AL + ao0);        CPA16(d1 + MM_REG, AL + ao1);
        CPA16(d0 + 2 * MM_REG, WH + wo0);    CPA16(d1 + 2 * MM_REG, WH + wo1);
        CPA16(d0 + 3 * MM_REG, WL + wo0);    CPA16(d1 + 3 * MM_REG, WL + wo1);
        CPCOMMIT();
    };

    issue(0);

    for (int kb = 0; kb < NKB; kb++) {
        CPWAIT(0);                        // buffer kb&1 fully landed
        __syncthreads();                  // all warps finished compute(kb-1)
        if (kb + 1 < NKB) issue(kb + 1);  // targets buf (kb+1)&1 = compute(kb-1)'s buf: free
        const uint32_t st = sb + (kb & 1) * MM_STAGE;
#pragma unroll
        for (int kh = 0; kh < 2; kh++) {
            const int kk = kh * 16;
            const uint32_t aoff = ((warp_m * 64 + (lane & 15)) * MM_LDS + kk + ((lane >> 4) << 3)) * 2;
            const uint32_t boff = ((warp_n * 32 + ((lane >> 4) << 3) + (lane & 7)) * MM_LDS
                                   + kk + (((lane >> 3) & 1) << 3)) * 2;
            uint32_t ah[4][4], bh[2][4], bl[2][4];
#pragma unroll
            for (int mt = 0; mt < 4; mt++)
                ldsm4(ah[mt][0], ah[mt][1], ah[mt][2], ah[mt][3],
                      st + aoff + mt * 16 * MM_LDS * 2);
#pragma unroll
            for (int p = 0; p < 2; p++) {
                ldsm4(bh[p][0], bh[p][1], bh[p][2], bh[p][3],
                      st + 2 * MM_REG + boff + p * 16 * MM_LDS * 2);
                ldsm4(bl[p][0], bl[p][1], bl[p][2], bl[p][3],
                      st + 3 * MM_REG + boff + p * 16 * MM_LDS * 2);
            }
#pragma unroll
            for (int mt = 0; mt < 4; mt++)
#pragma unroll
                for (int nt = 0; nt < 4; nt++) {
                    mma16816(acc[mt][nt], ah[mt], &bh[nt >> 1][(nt & 1) * 2]);
                    mma16816(acc[mt][nt], ah[mt], &bl[nt >> 1][(nt & 1) * 2]);
                }
            uint32_t al[4][4];
#pragma unroll
            for (int mt = 0; mt < 4; mt++)
                ldsm4(al[mt][0], al[mt][1], al[mt][2], al[mt][3],
                      st + MM_REG + aoff + mt * 16 * MM_LDS * 2);
#pragma unroll
            for (int mt = 0; mt < 4; mt++)
#pragma unroll
                for (int nt = 0; nt < 4; nt++)
                    mma16816(acc[mt][nt], al[mt], &bh[nt >> 1][(nt & 1) * 2]);
        }
    }

    const int g = lane >> 2, q = lane & 3;
#pragma unroll
    for (int mt = 0; mt < 4; mt++) {
        int row = m0 + warp_m * 64 + mt * 16 + g;
#pragma unroll
        for (int nt = 0; nt < 4; nt++) {
            int col = n0 + warp_n * 32 + nt * 8 + q * 2;
            if (col < Nn) {
                float b0 = bias[col], b1 = bias[col + 1];
                float* c0 = C + (size_t)row * Nn + col;
                float* c1 = C + (size_t)(row + 8) * Nn + col;
                c0[0] = acc[mt][nt][0] + b0; c0[1] = acc[mt][nt][1] + b1;
                c1[0] = acc[mt][nt][2] + b0; c1[1] = acc[mt][nt][3] + b1;
            }
        }
    }
}

// ---------------- prep ----------------
__global__ void ebias_kernel(const float* __restrict__ bV) {
    int m = blockIdx.x * 8 + (threadIdx.x >> 5);
    int lane = threadIdx.x & 31;
    const float4* er = (const float4*)(d_enc + (size_t)m * H2v);
    float s = 0.f;
#pragma unroll
    for (int it = 0; it < 8; it++) {
        float4 e4 = er[it * 32 + lane];
        float4 b4 = ((const float4*)bV)[it * 32 + lane];
        s += e4.x * b4.x + e4.y * b4.y + e4.z * b4.z + e4.w * b4.w;
    }
#pragma unroll
    for (int o = 16; o; o >>= 1) s += __shfl_xor_sync(0xffffffffu, s, o);
    if (lane == 0) d_eb[m] = s;
}

__global__ void init_prep_kernel(const int* __restrict__ x, const int* __restrict__ lens,
                                 const int* __restrict__ y, const float* __restrict__ WV) {
    int idx = blockIdx.x * blockDim.x + threadIdx.x;
    int stride = gridDim.x * blockDim.x;
    for (int i = idx; i < Tt * Bb * H2v; i += stride) d_enc[i] = 0.f;
    for (int i = idx; i < Bb * Hh; i += stride) {
        d_hf[0][i] = 0.f; d_hb[0][i] = 0.f; d_cf[i] = 0.f; d_cb[i] = 0.f;
    }
    for (int i = idx; i < 512; i += stride) d_zero[i] = 0.f;
    for (int i = idx; i < Hh * H2v; i += stride) {
        int h = i >> 10, j = i & 1023;
        d_WVt[i] = WV[j * Hh + h];
    }
    for (int i = idx; i < Tt * Bb; i += stride) {
        int t = i / Bb, b = i % Bb;
        d_tokF[i] = x[b * Tt + t];
        int p = lens[b] - 1 - t; if (p < 0) p = 0;
        d_tokB[i] = x[b * Tt + p];
    }
    for (int i = idx; i < OUTT * Bb; i += stride) {
        int t = i / Bb, b = i % Bb;
        d_tokD[i] = (t == 0) ? SOSv : y[b * OUTT + (t - 1)];
    }
}

// ---------------- small FFMA GEMM (h0/c0) ----------------
template <int BM, int BN, int BK, int TM, int TN>
__global__ void __launch_bounds__((BM / TM) * (BN / TN))
gemm_kernel(const float* __restrict__ A, int lda,
            const float* __restrict__ W, const float* __restrict__ bias,
            float* __restrict__ C, int M, int Nn, int K) {
    constexpr int NT = (BM / TM) * (BN / TN);
    __shared__ __align__(16) float As[BK][BM + 4];
    __shared__ __align__(16) float Bs[BK][BN + 4];
    const int tid = threadIdx.x;
    const int tx = tid % (BN / TN);
    const int ty = tid / (BN / TN);
    const int m0 = blockIdx.y * BM;
    const int n0 = blockIdx.x * BN;

    u64 acc2[TM][TN / 2];
#pragma unroll
    for (int i = 0; i < TM; i++)
#pragma unroll
        for (int j = 0; j < TN / 2; j++) acc2[i][j] = 0ULL;

    const int nK = K / BK;
    for (int kb = 0; kb < nK; kb++) {
        const int k0 = kb * BK;
#pragma unroll
        for (int l = 0; l < (BM * BK / 4) / NT; l++) {
            int i = tid + l * NT;
            int m = i / (BK / 4), kq = i % (BK / 4);
            float4 v = make_float4(0.f, 0.f, 0.f, 0.f);
            int gm = m0 + m;
            if (gm < M) v = *(const float4*)(A + (size_t)gm * lda + k0 + kq * 4);
            int kk = kq * 4;
            As[kk][m] = v.x; As[kk + 1][m] = v.y; As[kk + 2][m] = v.z; As[kk + 3][m] = v.w;
        }
#pragma unroll
        for (int l = 0; l < (BN * BK / 4) / NT; l++) {
            int i = tid + l * NT;
            int n = i / (BK / 4), kq = i % (BK / 4);
            float4 v = make_float4(0.f, 0.f, 0.f, 0.f);
            int gn = n0 + n;
            if (gn < Nn) v = *(const float4*)(W + (size_t)gn * K + k0 + kq * 4);
            int kk = kq * 4;
            Bs[kk][n] = v.x; Bs[kk + 1][n] = v.y; Bs[kk + 2][n] = v.z; Bs[kk + 3][n] = v.w;
        }
        __syncthreads();
#pragma unroll
        for (int k = 0; k < BK; k++) {
            float a[TM];
#pragma unroll
            for (int i = 0; i < TM; i += 4) {
                float4 v = *(const float4*)&As[k][ty * TM + i];
                a[i] = v.x; a[i + 1] = v.y; a[i + 2] = v.z; a[i + 3] = v.w;
            }
            u64 bb[TN / 2];
#pragma unroll
            for (int j = 0; j < TN; j += 4) {
                ulonglong2 v = *(const ulonglong2*)&Bs[k][tx * TN + j];
                bb[j / 2] = v.x; bb[j / 2 + 1] = v.y;
            }
#pragma unroll
            for (int i = 0; i < TM; i++) {
                u64 aa = pack2(a[i], a[i]);
#pragma unroll
                for (int j = 0; j < TN / 2; j++) acc2[i][j] = ffma2(aa, bb[j], acc2[i][j]);
            }
        }
        __syncthreads();
    }
#pragma unroll
    for (int i = 0; i < TM; i++) {
        int gm = m0 + ty * TM + i;
        if (gm >= M) continue;
        float* crow = C + (size_t)gm * Nn;
#pragma unroll
        for (int p = 0; p < TN / 2; p++) {
            float lo, hi; unpack2(acc2[i][p], lo, hi);
            int gn = n0 + tx * TN + 2 * p;
            if (gn < Nn)     crow[gn]     = lo + bias[gn];
            if (gn + 1 < Nn) crow[gn + 1] = hi + bias[gn + 1];
        }
    }
}

// ================= persistent encoder (blocks>=128 convert W_fc) =================
#define ENC_SMEM ((512 * 36 + 2 * 32 * 68 + 64 * 33) * 4)

__global__ void __launch_bounds__(256)
lstm_enc_persist(const float* __restrict__ Whf, const float* __restrict__ Whb,
                 const int* __restrict__ lens, const float* __restrict__ Wfc) {
    extern __shared__ float sm[];
    const int tid = threadIdx.x;
    const int bid = blockIdx.x;

    if (bid >= 128) {
        const int n4 = Vv * H3v / 4;
        for (int i = (bid - 128) * 256 + tid; i < n4; i += 20 * 256) {
            float4 v = ((const float4*)Wfc)[i];
            unsigned bx = __float_as_uint(v.x), by = __float_as_uint(v.y);
            unsigned bz = __float_as_uint(v.z), bw = __float_as_uint(v.w);
            unsigned h0 = (bx >> 16) | (by & 0xFFFF0000u);
            unsigned h1 = (bz >> 16) | (bw & 0xFFFF0000u);
            float rx = v.x - __uint_as_float(bx & 0xFFFF0000u);
            float ry = v.y - __uint_as_float(by & 0xFFFF0000u);
            float rz = v.z - __uint_as_float(bz & 0xFFFF0000u);
            float rw = v.w - __uint_as_float(bw & 0xFFFF0000u);
            ((uint2*)d_WfcH)[i] = make_uint2(h0, h1);
            ((uint2*)d_WfcL)[i] = make_uint2(pbf2(rx, ry), pbf2(rz, rw));
        }
        return;
    }

    float* Wt  = sm;
    float* Asb = sm + 512 * 36;
    float* gsm = Asb + 2 * 32 * 68;
    const int dir = bid >> 6;
    const int hb0 = (bid & 63) << 3;
    const float* Whh = dir ? Whb : Whf;
    float* cst = dir ? d_cb : d_cf;
    unsigned* bcnt = dir ? &d_bcE2 : &d_bcE;
    unsigned* bgen = dir ? &d_bgE2 : &d_bgE;

    for (int i = tid; i < 32 * 512; i += 256) {
        int n = i >> 9, k = i & 511;
        int grow = ((n >> 3) << 9) + hb0 + (n & 7);
        Wt[k * 36 + n] = Whh[(size_t)grow * 512 + k];
    }
    __syncthreads();

    const int tx = tid & 7, ty = tid >> 3;
    const int sm_m0 = tid >> 3, sm_kq0 = tid & 7;
    const int sm_m1 = (tid + 256) >> 3;

    int gidx8[8];
#pragma unroll
    for (int r = 0; r < 2; r++) {
        int p = tid + r * 256;
        int b = p >> 3, u = p & 7;
        gidx8[r * 4]     = b * H4v + hb0 + u;
        gidx8[r * 4 + 1] = b * H4v + 512 + hb0 + u;
        gidx8[r * 4 + 2] = b * H4v + 1024 + hb0 + u;
        gidx8[r * 4 + 3] = b * H4v + 1536 + hb0 + u;
    }

    auto stage_write = [&](float* A, float4 r0, float4 r1) {
        A[(sm_kq0 * 4 + 0) * 68 + sm_m0] = r0.x;
        A[(sm_kq0 * 4 + 1) * 68 + sm_m0] = r0.y;
        A[(sm_kq0 * 4 + 2) * 68 + sm_m0] = r0.z;
        A[(sm_kq0 * 4 + 3) * 68 + sm_m0] = r0.w;
        A[(sm_kq0 * 4 + 0) * 68 + sm_m1] = r1.x;
        A[(sm_kq0 * 4 + 1) * 68 + sm_m1] = r1.y;
        A[(sm_kq0 * 4 + 2) * 68 + sm_m1] = r1.z;
        A[(sm_kq0 * 4 + 3) * 68 + sm_m1] = r1.w;
    };

    for (int t = 0; t < Tt; t++) {
        const int cur = t & 1;
        const float* hprev = dir ? d_hb[cur] : d_hf[cur];
        float* hnext       = dir ? d_hb[cur ^ 1] : d_hf[cur ^ 1];
        const float* Gin = (dir ? d_GinB : d_GinF) + (size_t)t * Bb * H4v;

        float ginr[8];
#pragma unroll
        for (int r = 0; r < 8; r++) ginr[r] = __ldg(Gin + gidx8[r]);

        u64 acc[2][2] = {{0ULL, 0ULL}, {0ULL, 0ULL}};
        float4 r0 = *(const float4*)(hprev + sm_m0 * 512 + sm_kq0 * 4);
        float4 r1 = *(const float4*)(hprev + sm_m1 * 512 + sm_kq0 * 4);
        stage_write(Asb, r0, r1);
        __syncthreads();

        for (int kb = 0; kb < 16; kb++) {
            if (kb + 1 < 16) {
                int k0 = (kb + 1) * 32;
                r0 = *(const float4*)(hprev + sm_m0 * 512 + k0 + sm_kq0 * 4);
                r1 = *(const float4*)(hprev + sm_m1 * 512 + k0 + sm_kq0 * 4);
            }
            const float* A = Asb + (kb & 1) * 2176;
#pragma unroll
            for (int k = 0; k < 32; k++) {
                float2 a = *(const float2*)(A + k * 68 + ty * 2);
                ulonglong2 w = *(const ulonglong2*)(Wt + (kb * 32 + k) * 36 + tx * 4);
                u64 p0 = pack2(a.x, a.x), p1 = pack2(a.y, a.y);
                acc[0][0] = ffma2(p0, w.x, acc[0][0]);
                acc[0][1] = ffma2(p0, w.y, acc[0][1]);
                acc[1][0] = ffma2(p1, w.x, acc[1][0]);
                acc[1][1] = ffma2(p1, w.y, acc[1][1]);
            }
            if (kb + 1 < 16) stage_write(Asb + ((kb + 1) & 1) * 2176, r0, r1);
            __syncthreads();
        }
#pragma unroll
        for (int i = 0; i < 2; i++) {
            int m = ty * 2 + i;
#pragma unroll
            for (int p = 0; p < 2; p++) {
                float lo, hi; unpack2(acc[i][p], lo, hi);
                int j0 = tx * 4 + 2 * p;
                gsm[m * 33 + j0]     = lo;
                gsm[m * 33 + j0 + 1] = hi;
            }
        }
        __syncthreads();
#pragma unroll
        for (int r = 0; r < 2; r++) {
            int p = tid + r * 256;
            int b = p >> 3, u = p & 7;
            float gi = gsm[b * 33 + u]      + ginr[r * 4];
            float gf = gsm[b * 33 + 8 + u]  + ginr[r * 4 + 1];
            float gg = gsm[b * 33 + 16 + u] + ginr[r * 4 + 2];
            float go = gsm[b * 33 + 24 + u] + ginr[r * 4 + 3];
            int hidx = b * Hh + hb0 + u;
            bool msk = t < lens[b];
            float c_old = cst[hidx];
            float c2 = sigf(gf) * c_old + sigf(gi) * tanhf(gg);
            float h2 = sigf(go) * tanhf(c2);
            hnext[hidx] = msk ? h2 : hprev[hidx];
            if (msk) {
                cst[hidx] = c2;
                if (dir == 0) d_enc[((size_t)t * Bb + b) * H2v + hb0 + u] = h2;
                else {
                    int tout = lens[b] - 1 - t;
                    d_enc[((size_t)tout * Bb + b) * H2v + Hh + hb0 + u] = h2;
                }
            }
        }
        gridbar(bcnt, bgen, 64);
    }
}

// ================= persistent decoder (writes ctxH/ctxL split directly) =========
#define DEC_SMEM ((512 * 20 + 2 * 32 * 68 + 64 * 17 + 512 + 128 + 128) * 4)

__global__ void __launch_bounds__(256)
lstm_dec_persist(const float* __restrict__ Whd) {
    extern __shared__ float sm[];
    float* WtD = sm;
    float* Asb = WtD + 512 * 20;
    float* gsm = Asb + 2 * 32 * 68;
    float* qs  = gsm + 64 * 17;
    float* es  = qs + 512;
    float* as_ = es + 128;
    const int tid = threadIdx.x;
    const int bid = blockIdx.x;
    const int hb0 = bid << 2;
    const int ab  = bid & 63;
    const int half = bid >> 6;

    for (int i = tid; i < 16 * 512; i += 256) {
        int n = i >> 9, k = i & 511;
        int grow = ((n >> 2) << 9) + hb0 + (n & 3);
        WtD[k * 20 + n] = Whd[(size_t)grow * 512 + k];
    }
    __syncthreads();

    const int tx = tid & 7, ty = tid >> 3;
    const int sm_m0 = tid >> 3, sm_kq0 = tid & 7;
    const int sm_m1 = (tid + 256) >> 3;

    int gidx4[4];
    {
        int b = tid >> 2, u = tid & 3;
        gidx4[0] = b * H4v + hb0 + u;
        gidx4[1] = b * H4v + 512 + hb0 + u;
        gidx4[2] = b * H4v + 1024 + hb0 + u;
        gidx4[3] = b * H4v + 1536 + hb0 + u;
    }

    auto stage_write = [&](float* A, float4 r0, float4 r1) {
        A[(sm_kq0 * 4 + 0) * 68 + sm_m0] = r0.x;
        A[(sm_kq0 * 4 + 1) * 68 + sm_m0] = r0.y;
        A[(sm_kq0 * 4 + 2) * 68 + sm_m0] = r0.z;
        A[(sm_kq0 * 4 + 3) * 68 + sm_m0] = r0.w;
        A[(sm_kq0 * 4 + 0) * 68 + sm_m1] = r1.x;
        A[(sm_kq0 * 4 + 1) * 68 + sm_m1] = r1.y;
        A[(sm_kq0 * 4 + 2) * 68 + sm_m1] = r1.z;
        A[(sm_kq0 * 4 + 3) * 68 + sm_m1] = r1.w;
    };

    for (int t = 0; t < OUTT; t++) {
        const int cur = t & 1;
        const float* hprev = d_hd[cur];
        float* hnext       = d_hd[cur ^ 1];
        const float* Gin = d_GinD + (size_t)t * Bb * H4v;

        float ginr[4];
#pragma unroll
        for (int r = 0; r < 4; r++) ginr[r] = __ldg(Gin + gidx4[r]);

        u64 acc[2] = {0ULL, 0ULL};
        float4 r0 = *(const float4*)(hprev + sm_m0 * 512 + sm_kq0 * 4);
        float4 r1 = *(const float4*)(hprev + sm_m1 * 512 + sm_kq0 * 4);
        stage_write(Asb, r0, r1);
        __syncthreads();

        for (int kb = 0; kb < 16; kb++) {
            if (kb + 1 < 16) {
                int k0 = (kb + 1) * 32;
                r0 = *(const float4*)(hprev + sm_m0 * 512 + k0 + sm_kq0 * 4);
                r1 = *(const float4*)(hprev + sm_m1 * 512 + k0 + sm_kq0 * 4);
            }
            const float* A = Asb + (kb & 1) * 2176;
#pragma unroll
            for (int k = 0; k < 32; k++) {
                float2 a = *(const float2*)(A + k * 68 + ty * 2);
                u64 w = *(const u64*)(WtD + (kb * 32 + k) * 20 + tx * 2);
                acc[0] = ffma2(pack2(a.x, a.x), w, acc[0]);
                acc[1] = ffma2(pack2(a.y, a.y), w, acc[1]);
            }
            if (kb + 1 < 16) stage_write(Asb + ((kb + 1) & 1) * 2176, r0, r1);
            __syncthreads();
        }
#pragma unroll
        for (int i = 0; i < 2; i++) {
            int m = ty * 2 + i;
            float lo, hi; unpack2(acc[i], lo, hi);
            int n0 = tx * 2;
            gsm[m * 17 + n0]     = lo;
            gsm[m * 17 + n0 + 1] = hi;
        }
        __syncthreads();
        {
            int b = tid >> 2, u = tid & 3;
            float gi = gsm[b * 17 + u]      + ginr[0];
            float gf = gsm[b * 17 + 4 + u]  + ginr[1];
            float gg = gsm[b * 17 + 8 + u]  + ginr[2];
            float go = gsm[b * 17 + 12 + u] + ginr[3];
            int hidx = b * Hh + hb0 + u;
            float c_old = d_cd[hidx];
            float c2 = sigf(gf) * c_old + sigf(gi) * tanhf(gg);
            float h2 = sigf(go) * tanhf(c2);
            hnext[hidx] = h2;
            d_cd[hidx] = c2;
            size_t cidx = ((size_t)t * Bb + b) * H3v + H2v + hb0 + u;
            unsigned bits = __float_as_uint(h2);
            float rr = h2 - __uint_as_float(bits & 0xFFFF0000u);
            d_ctxH[cidx] = (u16)(bits >> 16);
            d_ctxL[cidx] = (u16)(pbf2(rr, rr) & 0xFFFFu);
        }
        gridbar(&d_bcD, &d_bgD, 128);

        const float* h2p = d_hd[cur ^ 1];
        if (tid < 128) ((float4*)qs)[tid] = ((const float4*)(h2p + (size_t)ab * Hh))[tid];
        __syncthreads();
        {
            int w = tid >> 5, lane = tid & 31;
#pragma unroll
            for (int i = 0; i < 16; i++) {
                int tt = w + 8 * i;
                const float4* Ep = (const float4*)(d_E + ((size_t)tt * Bb + ab) * Hh);
                float s = 0.f;
#pragma unroll
                for (int it = 0; it < 4; it++) {
                    int h4 = it * 32 + lane;
                    float4 e4 = Ep[h4];
                    float4 q4 = ((const float4*)qs)[h4];
                    s += e4.x * q4.x + e4.y * q4.y + e4.z * q4.z + e4.w * q4.w;
                }
#pragma unroll
                for (int o = 16; o; o >>= 1) s += __shfl_xor_sync(0xffffffffu, s, o);
                if (lane == 0) es[tt] = s + d_eb[tt * Bb + ab];
            }
        }
        __syncthreads();
        float mx = -1e30f;
        for (int i = 0; i < Tt; i++) mx = fmaxf(mx, es[i]);
        if (tid < Tt) as_[tid] = expf(es[tid] - mx);
        __syncthreads();
        float sum = 0.f;
        for (int i = 0; i < Tt; i++) sum += as_[i];
        float inv = 1.f / sum;
        if (tid < 128) {
            int idx4 = half * 128 + tid;
            float4 a4 = make_float4(0.f, 0.f, 0.f, 0.f);
            for (int tt = 0; tt < Tt; tt++) {
                int L = ab * Tt + tt;
                int t0 = L >> 6, b0 = L & 63;
                float4 e4 = ((const float4*)(d_enc + ((size_t)t0 * Bb + b0) * H2v))[idx4];
                float a = as_[tt];
                a4.x += a * e4.x; a4.y += a * e4.y; a4.z += a * e4.z; a4.w += a * e4.w;
            }
            a4.x *= inv; a4.y *= inv; a4.z *= inv; a4.w *= inv;
            size_t base = ((size_t)t * Bb + ab) * H3v + (size_t)idx4 * 4;
            unsigned b0_ = __float_as_uint(a4.x), b1_ = __float_as_uint(a4.y);
            unsigned b2_ = __float_as_uint(a4.z), b3_ = __float_as_uint(a4.w);
            unsigned h01 = (b0_ >> 16) | (b1_ & 0xFFFF0000u);
            unsigned h23 = (b2_ >> 16) | (b3_ & 0xFFFF0000u);
            float r0_ = a4.x - __uint_as_float(b0_ & 0xFFFF0000u);
            float r1_ = a4.y - __uint_as_float(b1_ & 0xFFFF0000u);
            float r2_ = a4.z - __uint_as_float(b2_ & 0xFFFF0000u);
            float r3_ = a4.w - __uint_as_float(b3_ & 0xFFFF0000u);
            *(uint2*)(d_ctxH + base) = make_uint2(h01, h23);
            *(uint2*)(d_ctxL + base) = make_uint2(pbf2(r0_, r1_), pbf2(r2_, r3_));
        }
        __syncthreads();
    }
}

// ---------------- concat final encoder states ----------------
__global__ void concat_hc() {
    int i = blockIdx.x * blockDim.x + threadIdx.x;
    if (i < Bb * H2v) {
        int b = i >> 10, h = i & 1023;
        d_hcat[i] = (h < Hh) ? d_hf[0][b * Hh + h] : d_hb[0][b * Hh + h - Hh];
        d_ccat[i] = (h < Hh) ? d_cf[b * Hh + h] : d_cb[b * Hh + h - Hh];
    }
}

// ---------------- host ----------------
static void* symaddr(const void* sym) {
    void* p = nullptr;
    cudaGetSymbolAddress(&p, sym);
    return p;
}

extern "C" void kernel_launch(void* const* d_in, const int* in_sizes, int n_in,
                              void* d_out, int out_size) {
    int s = (in_sizes[3] == 1) ? 4 : 3;
    const int*   x      = (const int*)d_in[0];
    const int*   lens   = (const int*)d_in[1];
    const int*   y      = (const int*)d_in[2];
    const float* emb_in = (const float*)d_in[s + 0];
    const float* emb_out= (const float*)d_in[s + 1];
    const float* W_ih_f = (const float*)d_in[s + 2];
    const float* W_hh_f = (const float*)d_in[s + 3];
    const float* b_f    = (const float*)d_in[s + 4];
    const float* W_ih_b = (const float*)d_in[s + 5];
    const float* W_hh_b = (const float*)d_in[s + 6];
    const float* b_b    = (const float*)d_in[s + 7];
    const float* W_rh   = (const float*)d_in[s + 8];
    const float* b_rh   = (const float*)d_in[s + 9];
    const float* W_rc   = (const float*)d_in[s + 10];
    const float* b_rc   = (const float*)d_in[s + 11];
    const float* W_ih_d = (const float*)d_in[s + 12];
    const float* W_hh_d = (const float*)d_in[s + 13];
    const float* b_d    = (const float*)d_in[s + 14];
    const float* W_V    = (const float*)d_in[s + 15];
    const float* b_V    = (const float*)d_in[s + 16];
    const float* W_fc   = (const float*)d_in[s + 17];
    const float* b_fc   = (const float*)d_in[s + 18];
    float* out = (float*)d_out;

    float* ginF = (float*)symaddr(d_GinF);
    float* ginB = (float*)symaddr(d_GinB);
    float* ginD = (float*)symaddr(d_GinD);
    float* hcat = (float*)symaddr(d_hcat);
    float* ccat = (float*)symaddr(d_ccat);
    float* hd   = (float*)symaddr(d_hd);
    float* cd   = (float*)symaddr(d_cd);
    float* enc  = (float*)symaddr(d_enc);
    float* Ebuf = (float*)symaddr(d_E);
    float* WVt  = (float*)symaddr(d_WVt);
    float* zer  = (float*)symaddr(d_zero);
    u16* WfcH = (u16*)symaddr(d_WfcH);
    u16* WfcL = (u16*)symaddr(d_WfcL);
    u16* ctxH = (u16*)symaddr(d_ctxH);
    u16* ctxL = (u16*)symaddr(d_ctxL);
    int* tokF = (int*)symaddr(d_tokF);
    int* tokB = (int*)symaddr(d_tokB);
    int* tokD = (int*)symaddr(d_tokD);

    static int attr_set = 0;
    if (!attr_set) {
        cudaFuncSetAttribute(mma_gemm_kernel<true>,
                             cudaFuncAttributeMaxDynamicSharedMemorySize, MM_SMEM);
        cudaFuncSetAttribute(mma_gemm_kernel<false>,
                             cudaFuncAttributeMaxDynamicSharedMemorySize, MM_SMEM);
        cudaFuncSetAttribute(fc_bf16_kernel,
                             cudaFuncAttributeMaxDynamicSharedMemorySize, MM_SMEM);
        cudaFuncSetAttribute(lstm_enc_persist,
                             cudaFuncAttributeMaxDynamicSharedMemorySize, ENC_SMEM);
        cudaFuncSetAttribute(lstm_dec_persist,
                             cudaFuncAttributeMaxDynamicSharedMemorySize, DEC_SMEM);
        attr_set = 1;
    }

    init_prep_kernel<<<512, 256>>>(x, lens, y, W_V);

    mma_gemm_kernel<true><<<dim3(Tt * Bb / 128, H4v / 128), 256, MM_SMEM>>>(
        emb_in, tokF, W_ih_f, b_f, ginF, H4v, Ee);
    mma_gemm_kernel<true><<<dim3(Tt * Bb / 128, H4v / 128), 256, MM_SMEM>>>(
        emb_in, tokB, W_ih_b, b_b, ginB, H4v, Ee);
    mma_gemm_kernel<true><<<dim3(OUTT * Bb / 128, H4v / 128), 256, MM_SMEM>>>(
        emb_out, tokD, W_ih_d, b_d, ginD, H4v, Ee);

    // encoder: 128 LSTM blocks + 20 spare blocks converting W_fc concurrently
    lstm_enc_persist<<<148, 256, ENC_SMEM>>>(W_hh_f, W_hh_b, lens, W_fc);

    concat_hc<<<(Bb * H2v + 255) / 256, 256>>>();
    gemm_kernel<64, 32, 16, 4, 4><<<dim3(Hh / 32, 1), 128>>>(
        hcat, H2v, W_rh, b_rh, hd, Bb, Hh, H2v);
    gemm_kernel<64, 32, 16, 4, 4><<<dim3(Hh / 32, 1), 128>>>(
        ccat, H2v, W_rc, b_rc, cd, Bb, Hh, H2v);

    mma_gemm_kernel<false><<<dim3(Tt * Bb / 128, Hh / 128), 256, MM_SMEM>>>(
        enc, nullptr, WVt, zer, Ebuf, Hh, H2v);
    ebias_kernel<<<Tt * Bb / 8, 256>>>(b_V);

    lstm_dec_persist<<<128, 256, DEC_SMEM>>>(W_hh_d);

    fc_bf16_kernel<<<dim3(OUTT * Bb / 128, (Vv + 127) / 128), 256, MM_SMEM>>>(
        ctxH, ctxL, WfcH, WfcL, b_fc, out, Vv, H3v);
}

// round 16
// speedup vs baseline: 1.1914x; 1.1248x over previous
#include <cuda_runtime.h>
#include <cstdint>
#include <math.h>

#define Bb   64
#define Tt   128
#define OUTT 64
#define Ee   256
#define Hh   512
#define H2v  1024
#define H3v  1536
#define H4v  2048
#define Vv   20000
#define SOSv 1

typedef unsigned long long u64;
typedef unsigned short u16;

// ---------------- scratch ----------------
__device__ float d_GinF[Tt * Bb * H4v];
__device__ float d_GinB[Tt * Bb * H4v];
__device__ float d_GinD[OUTT * Bb * H4v];
__device__ float d_enc[Tt * Bb * H2v];
__device__ float d_hf[2][Bb * Hh];
__device__ float d_hb[2][Bb * Hh];
__device__ float d_cf[Bb * Hh];
__device__ float d_cb[Bb * Hh];
__device__ float d_hd[2][Bb * Hh];
__device__ float d_cd[Bb * Hh];
__device__ float d_hcat[Bb * H2v];
__device__ float d_ccat[Bb * H2v];
__device__ float d_E[Tt * Bb * Hh];
__device__ float d_eb[Tt * Bb];
__device__ float d_WVt[Hh * H2v];
__device__ float d_zero[512];
__device__ u16  d_WfcH[(size_t)Vv * H3v];
__device__ u16  d_WfcL[(size_t)Vv * H3v];
__device__ u16  d_ctxH[OUTT * Bb * H3v];
__device__ u16  d_ctxL[OUTT * Bb * H3v];
__device__ int   d_tokF[Tt * Bb];
__device__ int   d_tokB[Tt * Bb];
__device__ int   d_tokD[OUTT * Bb];
__device__ unsigned d_bcE, d_bgE, d_bcE2, d_bgE2, d_bcD, d_bgD;

__device__ __forceinline__ float sigf(float x) { return 1.f / (1.f + expf(-x)); }

__device__ __forceinline__ u64 pack2(float lo, float hi) {
    u64 r; asm("mov.b64 %0, {%1, %2};" : "=l"(r) : "f"(lo), "f"(hi)); return r;
}
__device__ __forceinline__ void unpack2(u64 v, float& lo, float& hi) {
    unsigned int a, b;
    asm("mov.b64 {%0, %1}, %2;" : "=r"(a), "=r"(b) : "l"(v));
    lo = __uint_as_float(a); hi = __uint_as_float(b);
}
__device__ __forceinline__ u64 ffma2(u64 a, u64 b, u64 c) {
    u64 d; asm("fma.rn.f32x2 %0, %1, %2, %3;" : "=l"(d) : "l"(a), "l"(b), "l"(c)); return d;
}
__device__ __forceinline__ uint32_t smem_u32(const void* p) {
    uint32_t a;
    asm("{ .reg .u64 t; cvta.to.shared.u64 t, %1; cvt.u32.u64 %0, t; }" : "=r"(a) : "l"(p));
    return a;
}
__device__ __forceinline__ unsigned pbf2(float lo, float hi) {
    unsigned r; asm("cvt.rn.bf16x2.f32 %0, %1, %2;" : "=r"(r) : "f"(hi), "f"(lo)); return r;
}
__device__ __forceinline__ void ldsm4(uint32_t& r0, uint32_t& r1, uint32_t& r2, uint32_t& r3,
                                      uint32_t addr) {
    asm volatile("ldmatrix.sync.aligned.m8n8.x4.shared.b16 {%0,%1,%2,%3}, [%4];"
                 : "=r"(r0), "=r"(r1), "=r"(r2), "=r"(r3) : "r"(addr));
}
__device__ __forceinline__ void mma16816(float* c, const uint32_t* a, const uint32_t* b) {
    asm volatile("mma.sync.aligned.m16n8k16.row.col.f32.bf16.bf16.f32 "
                 "{%0,%1,%2,%3}, {%4,%5,%6,%7}, {%8,%9}, {%0,%1,%2,%3};"
                 : "+f"(c[0]), "+f"(c[1]), "+f"(c[2]), "+f"(c[3])
                 : "r"(a[0]), "r"(a[1]), "r"(a[2]), "r"(a[3]), "r"(b[0]), "r"(b[1]));
}
#define CPA16(dst, src) asm volatile("cp.async.cg.shared.global [%0], [%1], 16;" :: "r"(dst), "l"(src))
#define CPCOMMIT()      asm volatile("cp.async.commit_group;" ::: "memory")
#define CPWAIT(n)       asm volatile("cp.async.wait_group %0;" :: "n"(n) : "memory")

// ---------------- grid barrier (tight spin) ----------------
__device__ __forceinline__ void gridbar(unsigned* cnt, unsigned* gen, unsigned nb) {
    __syncthreads();
    if (threadIdx.x == 0) {
        __threadfence();
        volatile unsigned* vg = gen;
        unsigned g = *vg;
        if (atomicInc(cnt, nb - 1) == nb - 1) {
            *vg = g + 1;
        } else {
            while (*vg == g) { }
        }
    }
    __syncthreads();
}

#define MM_LDS   40
#define MM_REG   10240
#define MM_STAGE (4 * MM_REG)
#define MM_SMEM  (2 * MM_STAGE)

// ======================= fp32-input HMMA split GEMM (gathers + E) ==============
template <bool GATHER>
__global__ void __launch_bounds__(256)
mma_gemm_kernel(const float* __restrict__ A, const int* __restrict__ gidx,
                const float* __restrict__ W, const float* __restrict__ bias,
                float* __restrict__ C, int Nn, int K) {
    extern __shared__ char smem[];
    const uint32_t sb = smem_u32(smem);
    const int tid = threadIdx.x, wid = tid >> 5, lane = tid & 31;
    const int warp_m = wid & 1, warp_n = wid >> 1;
    const int m0 = blockIdx.x * 128;
    const int n0 = blockIdx.y * 128;
    const int NKB = K / 32;

    float acc[4][4][4];
#pragma unroll
    for (int mt = 0; mt < 4; mt++)
#pragma unroll
        for (int nt = 0; nt < 4; nt++)
#pragma unroll
            for (int i = 0; i < 4; i++) acc[mt][nt][i] = 0.f;

    const int grow = tid >> 3, gkq = tid & 7;
    float4 ga[4], gb[4];

    auto gload = [&](int s) {
        const int k0 = s * 32;
#pragma unroll
        for (int r = 0; r < 4; r++) {
            int m = grow + r * 32;
            const float* ap = GATHER ? (A + (size_t)gidx[m0 + m] * K)
                                     : (A + (size_t)(m0 + m) * K);
            ga[r] = *(const float4*)(ap + k0 + gkq * 4);
            int gn = n0 + m;
            gb[r] = (gn < Nn) ? *(const float4*)(W + (size_t)gn * K + k0 + gkq * 4)
                              : make_float4(0.f, 0.f, 0.f, 0.f);
        }
    };
    auto cvst = [&](char* base, float4 v, int off) {
        unsigned bx = __float_as_uint(v.x), by = __float_as_uint(v.y);
        unsigned bz = __float_as_uint(v.z), bw = __float_as_uint(v.w);
        unsigned h0 = (bx >> 16) | (by & 0xFFFF0000u);
        unsigned h1 = (bz >> 16) | (bw & 0xFFFF0000u);
        float rx = v.x - __uint_as_float(bx & 0xFFFF0000u);
        float ry = v.y - __uint_as_float(by & 0xFFFF0000u);
        float rz = v.z - __uint_as_float(bz & 0xFFFF0000u);
        float rw = v.w - __uint_as_float(bw & 0xFFFF0000u);
        *(uint2*)(base + off)          = make_uint2(h0, h1);
        *(uint2*)(base + MM_REG + off) = make_uint2(pbf2(rx, ry), pbf2(rz, rw));
    };
    auto sstore = [&](int buf) {
        char* st = smem + buf * MM_STAGE;
#pragma unroll
        for (int r = 0; r < 4; r++) {
            int off = (grow + r * 32) * 80 + gkq * 8;
            cvst(st, ga[r], off);
            cvst(st + 2 * MM_REG, gb[r], off);
        }
    };

    gload(0); sstore(0); __syncthreads();

    for (int kb = 0; kb < NKB; kb++) {
        if (kb + 1 < NKB) gload(kb + 1);
        const uint32_t st = sb + (kb & 1) * MM_STAGE;
#pragma unroll
        for (int kh = 0; kh < 2; kh++) {
            const int kk = kh * 16;
            const uint32_t aoff = ((warp_m * 64 + (lane & 15)) * MM_LDS + kk + ((lane >> 4) << 3)) * 2;
            const uint32_t boff = ((warp_n * 32 + ((lane >> 4) << 3) + (lane & 7)) * MM_LDS
                                   + kk + (((lane >> 3) & 1) << 3)) * 2;
            uint32_t ah[4][4], bh[2][4], bl[2][4];
#pragma unroll
            for (int mt = 0; mt < 4; mt++)
                ldsm4(ah[mt][0], ah[mt][1], ah[mt][2], ah[mt][3],
                      st + aoff + mt * 16 * MM_LDS * 2);
#pragma unroll
            for (int p = 0; p < 2; p++) {
                ldsm4(bh[p][0], bh[p][1], bh[p][2], bh[p][3],
                      st + 2 * MM_REG + boff + p * 16 * MM_LDS * 2);
                ldsm4(bl[p][0], bl[p][1], bl[p][2], bl[p][3],
                      st + 3 * MM_REG + boff + p * 16 * MM_LDS * 2);
            }
#pragma unroll
            for (int mt = 0; mt < 4; mt++)
#pragma unroll
                for (int nt = 0; nt < 4; nt++) {
                    mma16816(acc[mt][nt], ah[mt], &bh[nt >> 1][(nt & 1) * 2]);
                    mma16816(acc[mt][nt], ah[mt], &bl[nt >> 1][(nt & 1) * 2]);
                }
            uint32_t al[4][4];
#pragma unroll
            for (int mt = 0; mt < 4; mt++)
                ldsm4(al[mt][0], al[mt][1], al[mt][2], al[mt][3],
                      st + MM_REG + aoff + mt * 16 * MM_LDS * 2);
#pragma unroll
            for (int mt = 0; mt < 4; mt++)
#pragma unroll
                for (int nt = 0; nt < 4; nt++)
                    mma16816(acc[mt][nt], al[mt], &bh[nt >> 1][(nt & 1) * 2]);
        }
        if (kb + 1 < NKB) sstore((kb + 1) & 1);
        __syncthreads();
    }

    const int g = lane >> 2, q = lane & 3;
#pragma unroll
    for (int mt = 0; mt < 4; mt++) {
        int row = m0 + warp_m * 64 + mt * 16 + g;
#pragma unroll
        for (int nt = 0; nt < 4; nt++) {
            int col = n0 + warp_n * 32 + nt * 8 + q * 2;
            if (col < Nn) {
                float b0 = bias[col], b1 = bias[col + 1];
                float* c0 = C + (size_t)row * Nn + col;
                float* c1 = C + (size_t)(row + 8) * Nn + col;
                c0[0] = acc[mt][nt][0] + b0; c0[1] = acc[mt][nt][1] + b1;
                c1[0] = acc[mt][nt][2] + b0; c1[1] = acc[mt][nt][3] + b1;
            }
        }
    }
}

// ======= FC: bf16-preconverted, 2 CTAs/SM, ONE sync per K-block =======
__global__ void __launch_bounds__(256, 2)
fc_bf16_kernel(const u16* __restrict__ AH, const u16* __restrict__ AL,
               const u16* __restrict__ WH, const u16* __restrict__ WL,
               const float* __restrict__ bias, float* __restrict__ C,
               int Nn, int K) {
    extern __shared__ char smem[];
    const uint32_t sb = smem_u32(smem);
    const int tid = threadIdx.x, wid = tid >> 5, lane = tid & 31;
    const int warp_m = wid & 1, warp_n = wid >> 1;
    const int m0 = blockIdx.x * 128;
    const int n0 = blockIdx.y * 128;
    const int NKB = K / 32;

    float acc[4][4][4];
#pragma unroll
    for (int mt = 0; mt < 4; mt++)
#pragma unroll
        for (int nt = 0; nt < 4; nt++)
#pragma unroll
            for (int i = 0; i < 4; i++) acc[mt][nt][i] = 0.f;

    const int lrow0 = tid >> 2, lkq0 = tid & 3;
    const int lrow1 = (tid + 256) >> 2;
    const int wrowc = (n0 + lrow0 < Nn) ? (n0 + lrow0) : (Nn - 1);
    const int wrowc1 = (n0 + lrow1 < Nn) ? (n0 + lrow1) : (Nn - 1);

    auto issue = [&](int s) {
        const int buf = s & 1;
        const int k0 = s * 32;
        const uint32_t st = sb + buf * MM_STAGE;
        uint32_t d0 = st + lrow0 * 80 + lkq0 * 16;
        uint32_t d1 = st + lrow1 * 80 + lkq0 * 16;
        size_t ao0 = (size_t)(m0 + lrow0) * K + k0 + lkq0 * 8;
        size_t ao1 = (size_t)(m0 + lrow1) * K + k0 + lkq0 * 8;
        size_t wo0 = (size_t)wrowc * K + k0 + lkq0 * 8;
        size_t wo1 = (size_t)wrowc1 * K + k0 + lkq0 * 8;
        CPA16(d0, AH + ao0);                 CPA16(d1, AH + ao1);
        CPA16(d0 + MM_REG, AL + ao0);        CPA16(d1 + MM_REG, AL + ao1);
        CPA16(d0 + 2 * MM_REG, WH + wo0);    CPA16(d1 + 2 * MM_REG, WH + wo1);
        CPA16(d0 + 3 * MM_REG, WL + wo0);    CPA16(d1 + 3 * MM_REG, WL + wo1);
        CPCOMMIT();
    };

    issue(0);

    for (int kb = 0; kb < NKB; kb++) {
        CPWAIT(0);
        __syncthreads();
        if (kb + 1 < NKB) issue(kb + 1);
        const uint32_t st = sb + (kb & 1) * MM_STAGE;
#pragma unroll
        for (int kh = 0; kh < 2; kh++) {
            const int kk = kh * 16;
            const uint32_t aoff = ((warp_m * 64 + (lane & 15)) * MM_LDS + kk + ((lane >> 4) << 3)) * 2;
            const uint32_t boff = ((warp_n * 32 + ((lane >> 4) << 3) + (lane & 7)) * MM_LDS
                                   + kk + (((lane >> 3) & 1) << 3)) * 2;
            uint32_t ah[4][4], bh[2][4], bl[2][4];
#pragma unroll
            for (int mt = 0; mt < 4; mt++)
                ldsm4(ah[mt][0], ah[mt][1], ah[mt][2], ah[mt][3],
                      st + aoff + mt * 16 * MM_LDS * 2);
#pragma unroll
            for (int p = 0; p < 2; p++) {
                ldsm4(bh[p][0], bh[p][1], bh[p][2], bh[p][3],
                      st + 2 * MM_REG + boff + p * 16 * MM_LDS * 2);
                ldsm4(bl[p][0], bl[p][1], bl[p][2], bl[p][3],
                      st + 3 * MM_REG + boff + p * 16 * MM_LDS * 2);
            }
#pragma unroll
            for (int mt = 0; mt < 4; mt++)
#pragma unroll
                for (int nt = 0; nt < 4; nt++) {
                    mma16816(acc[mt][nt], ah[mt], &bh[nt >> 1][(nt & 1) * 2]);
                    mma16816(acc[mt][nt], ah[mt], &bl[nt >> 1][(nt & 1) * 2]);
                }
            uint32_t al[4][4];
#pragma unroll
            for (int mt = 0; mt < 4; mt++)
                ldsm4(al[mt][0], al[mt][1], al[mt][2], al[mt][3],
                      st + MM_REG + aoff + mt * 16 * MM_LDS * 2);
#pragma unroll
            for (int mt = 0; mt < 4; mt++)
#pragma unroll
                for (int nt = 0; nt < 4; nt++)
                    mma16816(acc[mt][nt], al[mt], &bh[nt >> 1][(nt & 1) * 2]);
        }
    }

    const int g = lane >> 2, q = lane & 3;
#pragma unroll
    for (int mt = 0; mt < 4; mt++) {
        int row = m0 + warp_m * 64 + mt * 16 + g;
#pragma unroll
        for (int nt = 0; nt < 4; nt++) {
            int col = n0 + warp_n * 32 + nt * 8 + q * 2;
            if (col < Nn) {
                float b0 = bias[col], b1 = bias[col + 1];
                float* c0 = C + (size_t)row * Nn + col;
                float* c1 = C + (size_t)(row + 8) * Nn + col;
                c0[0] = acc[mt][nt][0] + b0; c0[1] = acc[mt][nt][1] + b1;
                c1[0] = acc[mt][nt][2] + b0; c1[1] = acc[mt][nt][3] + b1;
            }
        }
    }
}

// ---------------- prep ----------------
__global__ void ebias_kernel(const float* __restrict__ bV) {
    int m = blockIdx.x * 8 + (threadIdx.x >> 5);
    int lane = threadIdx.x & 31;
    const float4* er = (const float4*)(d_enc + (size_t)m * H2v);
    float s = 0.f;
#pragma unroll
    for (int it = 0; it < 8; it++) {
        float4 e4 = er[it * 32 + lane];
        float4 b4 = ((const float4*)bV)[it * 32 + lane];
        s += e4.x * b4.x + e4.y * b4.y + e4.z * b4.z + e4.w * b4.w;
    }
#pragma unroll
    for (int o = 16; o; o >>= 1) s += __shfl_xor_sync(0xffffffffu, s, o);
    if (lane == 0) d_eb[m] = s;
}

__global__ void init_prep_kernel(const int* __restrict__ x, const int* __restrict__ lens,
                                 const int* __restrict__ y, const float* __restrict__ WV) {
    int idx = blockIdx.x * blockDim.x + threadIdx.x;
    int stride = gridDim.x * blockDim.x;
    for (int i = idx; i < Tt * Bb * H2v; i += stride) d_enc[i] = 0.f;
    for (int i = idx; i < Bb * Hh; i += stride) {
        d_hf[0][i] = 0.f; d_hb[0][i] = 0.f; d_cf[i] = 0.f; d_cb[i] = 0.f;
    }
    for (int i = idx; i < 512; i += stride) d_zero[i] = 0.f;
    for (int i = idx; i < Hh * H2v; i += stride) {
        int h = i >> 10, j = i & 1023;
        d_WVt[i] = WV[j * Hh + h];
    }
    for (int i = idx; i < Tt * Bb; i += stride) {
        int t = i / Bb, b = i % Bb;
        d_tokF[i] = x[b * Tt + t];
        int p = lens[b] - 1 - t; if (p < 0) p = 0;
        d_tokB[i] = x[b * Tt + p];
    }
    for (int i = idx; i < OUTT * Bb; i += stride) {
        int t = i / Bb, b = i % Bb;
        d_tokD[i] = (t == 0) ? SOSv : y[b * OUTT + (t - 1)];
    }
}

// ---------------- small FFMA GEMM (h0/c0) ----------------
template <int BM, int BN, int BK, int TM, int TN>
__global__ void __launch_bounds__((BM / TM) * (BN / TN))
gemm_kernel(const float* __restrict__ A, int lda,
            const float* __restrict__ W, const float* __restrict__ bias,
            float* __restrict__ C, int M, int Nn, int K) {
    constexpr int NT = (BM / TM) * (BN / TN);
    __shared__ __align__(16) float As[BK][BM + 4];
    __shared__ __align__(16) float Bs[BK][BN + 4];
    const int tid = threadIdx.x;
    const int tx = tid % (BN / TN);
    const int ty = tid / (BN / TN);
    const int m0 = blockIdx.y * BM;
    const int n0 = blockIdx.x * BN;

    u64 acc2[TM][TN / 2];
#pragma unroll
    for (int i = 0; i < TM; i++)
#pragma unroll
        for (int j = 0; j < TN / 2; j++) acc2[i][j] = 0ULL;

    const int nK = K / BK;
    for (int kb = 0; kb < nK; kb++) {
        const int k0 = kb * BK;
#pragma unroll
        for (int l = 0; l < (BM * BK / 4) / NT; l++) {
            int i = tid + l * NT;
            int m = i / (BK / 4), kq = i % (BK / 4);
            float4 v = make_float4(0.f, 0.f, 0.f, 0.f);
            int gm = m0 + m;
            if (gm < M) v = *(const float4*)(A + (size_t)gm * lda + k0 + kq * 4);
            int kk = kq * 4;
            As[kk][m] = v.x; As[kk + 1][m] = v.y; As[kk + 2][m] = v.z; As[kk + 3][m] = v.w;
        }
#pragma unroll
        for (int l = 0; l < (BN * BK / 4) / NT; l++) {
            int i = tid + l * NT;
            int n = i / (BK / 4), kq = i % (BK / 4);
            float4 v = make_float4(0.f, 0.f, 0.f, 0.f);
            int gn = n0 + n;
            if (gn < Nn) v = *(const float4*)(W + (size_t)gn * K + k0 + kq * 4);
            int kk = kq * 4;
            Bs[kk][n] = v.x; Bs[kk + 1][n] = v.y; Bs[kk + 2][n] = v.z; Bs[kk + 3][n] = v.w;
        }
        __syncthreads();
#pragma unroll
        for (int k = 0; k < BK; k++) {
            float a[TM];
#pragma unroll
            for (int i = 0; i < TM; i += 4) {
                float4 v = *(const float4*)&As[k][ty * TM + i];
                a[i] = v.x; a[i + 1] = v.y; a[i + 2] = v.z; a[i + 3] = v.w;
            }
            u64 bb[TN / 2];
#pragma unroll
            for (int j = 0; j < TN; j += 4) {
                ulonglong2 v = *(const ulonglong2*)&Bs[k][tx * TN + j];
                bb[j / 2] = v.x; bb[j / 2 + 1] = v.y;
            }
#pragma unroll
            for (int i = 0; i < TM; i++) {
                u64 aa = pack2(a[i], a[i]);
#pragma unroll
                for (int j = 0; j < TN / 2; j++) acc2[i][j] = ffma2(aa, bb[j], acc2[i][j]);
            }
        }
        __syncthreads();
    }
#pragma unroll
    for (int i = 0; i < TM; i++) {
        int gm = m0 + ty * TM + i;
        if (gm >= M) continue;
        float* crow = C + (size_t)gm * Nn;
#pragma unroll
        for (int p = 0; p < TN / 2; p++) {
            float lo, hi; unpack2(acc2[i][p], lo, hi);
            int gn = n0 + tx * TN + 2 * p;
            if (gn < Nn)     crow[gn]     = lo + bias[gn];
            if (gn + 1 < Nn) crow[gn + 1] = hi + bias[gn + 1];
        }
    }
}

// ================= persistent encoder: HMMA recurrence (blocks>=128 convert W_fc) ====
// smem: WhH 40960 B | WhL 40960 B | A stage 2x(AH 5120 + AL 5120) | gsm 64x33 f32
#define ENC_WHH  0
#define ENC_WHL  40960
#define ENC_AB   81920
#define ENC_GSM  102400
#define ENC_SMEM (102400 + 64 * 33 * 4)

__global__ void __launch_bounds__(256)
lstm_enc_persist(const float* __restrict__ Whf, const float* __restrict__ Whb,
                 const int* __restrict__ lens, const float* __restrict__ Wfc) {
    extern __shared__ char smem[];
    const int tid = threadIdx.x;
    const int bid = blockIdx.x;

    if (bid >= 128) {
        const int n4 = Vv * H3v / 4;
        for (int i = (bid - 128) * 256 + tid; i < n4; i += 20 * 256) {
            float4 v = ((const float4*)Wfc)[i];
            unsigned bx = __float_as_uint(v.x), by = __float_as_uint(v.y);
            unsigned bz = __float_as_uint(v.z), bw = __float_as_uint(v.w);
            unsigned h0 = (bx >> 16) | (by & 0xFFFF0000u);
            unsigned h1 = (bz >> 16) | (bw & 0xFFFF0000u);
            float rx = v.x - __uint_as_float(bx & 0xFFFF0000u);
            float ry = v.y - __uint_as_float(by & 0xFFFF0000u);
            float rz = v.z - __uint_as_float(bz & 0xFFFF0000u);
            float rw = v.w - __uint_as_float(bw & 0xFFFF0000u);
            ((uint2*)d_WfcH)[i] = make_uint2(h0, h1);
            ((uint2*)d_WfcL)[i] = make_uint2(pbf2(rx, ry), pbf2(rz, rw));
        }
        return;
    }

    const uint32_t sb = smem_u32(smem);
    u16* WhH = (u16*)(smem + ENC_WHH);
    u16* WhL = (u16*)(smem + ENC_WHL);
    float* gsm = (float*)(smem + ENC_GSM);
    const int wid = tid >> 5, lane = tid & 31;
    const int warp_m = wid & 3, warp_n = wid >> 2;      // 4 x 2 warps -> m64 x n32
    const int dir = bid >> 6;
    const int hb0 = (bid & 63) << 3;
    const float* Whh = dir ? Whb : Whf;
    float* cst = dir ? d_cb : d_cf;
    unsigned* bcnt = dir ? &d_bcE2 : &d_bcE;
    unsigned* bgen = dir ? &d_bgE2 : &d_bgE;

    // preconvert Whh slice [32 gate-cols][512] -> bf16 hi/lo, 16 chunks of [32][MM_LDS]
    for (int i = tid; i < 32 * 512; i += 256) {
        int n = i >> 9, k = i & 511;
        int grow = ((n >> 3) << 9) + hb0 + (n & 7);
        float v = Whh[(size_t)grow * 512 + k];
        unsigned bits = __float_as_uint(v);
        float lo = v - __uint_as_float(bits & 0xFFFF0000u);
        int off = (k >> 5) * (32 * MM_LDS) + n * MM_LDS + (k & 31);
        WhH[off] = (u16)(bits >> 16);
        WhL[off] = (u16)(pbf2(lo, lo) & 0xFFFFu);
    }
    __syncthreads();

    const int srow = tid >> 2, skq = tid & 3;           // h stage map: 64 rows x 8 k
    int gidx8[8];
#pragma unroll
    for (int r = 0; r < 2; r++) {
        int p = tid + r * 256;
        int b = p >> 3, u = p & 7;
        gidx8[r * 4]     = b * H4v + hb0 + u;
        gidx8[r * 4 + 1] = b * H4v + 512 + hb0 + u;
        gidx8[r * 4 + 2] = b * H4v + 1024 + hb0 + u;
        gidx8[r * 4 + 3] = b * H4v + 1536 + hb0 + u;
    }

    auto cvst2 = [&](char* base, float4 v, int off) {   // hi at off, lo at off+5120
        unsigned bx = __float_as_uint(v.x), by = __float_as_uint(v.y);
        unsigned bz = __float_as_uint(v.z), bw = __float_as_uint(v.w);
        unsigned h0 = (bx >> 16) | (by & 0xFFFF0000u);
        unsigned h1 = (bz >> 16) | (bw & 0xFFFF0000u);
        float rx = v.x - __uint_as_float(bx & 0xFFFF0000u);
        float ry = v.y - __uint_as_float(by & 0xFFFF0000u);
        float rz = v.z - __uint_as_float(bz & 0xFFFF0000u);
        float rw = v.w - __uint_as_float(bw & 0xFFFF0000u);
        *(uint2*)(base + off)        = make_uint2(h0, h1);
        *(uint2*)(base + 5120 + off) = make_uint2(pbf2(rx, ry), pbf2(rz, rw));
    };
    auto stage = [&](int buf, float4 v0, float4 v1) {
        char* base = smem + ENC_AB + buf * 10240;
        int off = srow * 80 + skq * 16;
        cvst2(base, v0, off);
        cvst2(base, v1, off + 8);
    };

    for (int t = 0; t < Tt; t++) {
        const int cur = t & 1;
        const float* hprev = dir ? d_hb[cur] : d_hf[cur];
        float* hnext       = dir ? d_hb[cur ^ 1] : d_hf[cur ^ 1];
        const float* Gin = (dir ? d_GinB : d_GinF) + (size_t)t * Bb * H4v;

        float ginr[8];
#pragma unroll
        for (int r = 0; r < 8; r++) ginr[r] = __ldg(Gin + gidx8[r]);

        float acc[2][4];
#pragma unroll
        for (int nt = 0; nt < 2; nt++)
#pragma unroll
            for (int i = 0; i < 4; i++) acc[nt][i] = 0.f;

        const float* hsrc = hprev + srow * 512 + skq * 8;
        float4 v0 = *(const float4*)hsrc;
        float4 v1 = *(const float4*)(hsrc + 4);
        stage(0, v0, v1);
        __syncthreads();

        for (int kb = 0; kb < 16; kb++) {
            if (kb + 1 < 16) {
                v0 = *(const float4*)(hsrc + (kb + 1) * 32);
                v1 = *(const float4*)(hsrc + (kb + 1) * 32 + 4);
            }
            const uint32_t stA = sb + ENC_AB + (kb & 1) * 10240;
            const uint32_t stB = sb + kb * (32 * MM_LDS * 2);
#pragma unroll
            for (int kh = 0; kh < 2; kh++) {
                const int kk = kh * 16;
                const uint32_t aoff = ((warp_m * 16 + (lane & 15)) * MM_LDS + kk + ((lane >> 4) << 3)) * 2;
                const uint32_t boff = ((warp_n * 16 + ((lane >> 4) << 3) + (lane & 7)) * MM_LDS
                                       + kk + (((lane >> 3) & 1) << 3)) * 2;
                uint32_t ah[4], al[4], bh[4], bl[4];
                ldsm4(ah[0], ah[1], ah[2], ah[3], stA + aoff);
                ldsm4(al[0], al[1], al[2], al[3], stA + 5120 + aoff);
                ldsm4(bh[0], bh[1], bh[2], bh[3], stB + ENC_WHH + boff);
                ldsm4(bl[0], bl[1], bl[2], bl[3], stB + ENC_WHL + boff);
#pragma unroll
                for (int nt = 0; nt < 2; nt++) {
                    mma16816(acc[nt], ah, &bh[nt * 2]);
                    mma16816(acc[nt], ah, &bl[nt * 2]);
                    mma16816(acc[nt], al, &bh[nt * 2]);
                }
            }
            if (kb + 1 < 16) stage((kb + 1) & 1, v0, v1);
            __syncthreads();
        }
        // epilogue: warp tile m16 x n16 -> gsm
        {
            int g = lane >> 2, q = lane & 3;
#pragma unroll
            for (int nt = 0; nt < 2; nt++) {
                int row = warp_m * 16 + g;
                int col = warp_n * 16 + nt * 8 + q * 2;
                gsm[row * 33 + col]           = acc[nt][0];
                gsm[row * 33 + col + 1]       = acc[nt][1];
                gsm[(row + 8) * 33 + col]     = acc[nt][2];
                gsm[(row + 8) * 33 + col + 1] = acc[nt][3];
            }
        }
        __syncthreads();
#pragma unroll
        for (int r = 0; r < 2; r++) {
            int p = tid + r * 256;
            int b = p >> 3, u = p & 7;
            float gi = gsm[b * 33 + u]      + ginr[r * 4];
            float gf = gsm[b * 33 + 8 + u]  + ginr[r * 4 + 1];
            float gg = gsm[b * 33 + 16 + u] + ginr[r * 4 + 2];
            float go = gsm[b * 33 + 24 + u] + ginr[r * 4 + 3];
            int hidx = b * Hh + hb0 + u;
            bool msk = t < lens[b];
            float c_old = cst[hidx];
            float c2 = sigf(gf) * c_old + sigf(gi) * tanhf(gg);
            float h2 = sigf(go) * tanhf(c2);
            hnext[hidx] = msk ? h2 : hprev[hidx];
            if (msk) {
                cst[hidx] = c2;
                if (dir == 0) d_enc[((size_t)t * Bb + b) * H2v + hb0 + u] = h2;
                else {
                    int tout = lens[b] - 1 - t;
                    d_enc[((size_t)tout * Bb + b) * H2v + Hh + hb0 + u] = h2;
                }
            }
        }
        gridbar(bcnt, bgen, 64);
    }
}

// ================= persistent decoder (unchanged) =========
#define DEC_SMEM ((512 * 20 + 2 * 32 * 68 + 64 * 17 + 512 + 128 + 128) * 4)

__global__ void __launch_bounds__(256)
lstm_dec_persist(const float* __restrict__ Whd) {
    extern __shared__ float sm[];
    float* WtD = sm;
    float* Asb = WtD + 512 * 20;
    float* gsm = Asb + 2 * 32 * 68;
    float* qs  = gsm + 64 * 17;
    float* es  = qs + 512;
    float* as_ = es + 128;
    const int tid = threadIdx.x;
    const int bid = blockIdx.x;
    const int hb0 = bid << 2;
    const int ab  = bid & 63;
    const int half = bid >> 6;

    for (int i = tid; i < 16 * 512; i += 256) {
        int n = i >> 9, k = i & 511;
        int grow = ((n >> 2) << 9) + hb0 + (n & 3);
        WtD[k * 20 + n] = Whd[(size_t)grow * 512 + k];
    }
    __syncthreads();

    const int tx = tid & 7, ty = tid >> 3;
    const int sm_m0 = tid >> 3, sm_kq0 = tid & 7;
    const int sm_m1 = (tid + 256) >> 3;

    int gidx4[4];
    {
        int b = tid >> 2, u = tid & 3;
        gidx4[0] = b * H4v + hb0 + u;
        gidx4[1] = b * H4v + 512 + hb0 + u;
        gidx4[2] = b * H4v + 1024 + hb0 + u;
        gidx4[3] = b * H4v + 1536 + hb0 + u;
    }

    auto stage_write = [&](float* A, float4 r0, float4 r1) {
        A[(sm_kq0 * 4 + 0) * 68 + sm_m0] = r0.x;
        A[(sm_kq0 * 4 + 1) * 68 + sm_m0] = r0.y;
        A[(sm_kq0 * 4 + 2) * 68 + sm_m0] = r0.z;
        A[(sm_kq0 * 4 + 3) * 68 + sm_m0] = r0.w;
        A[(sm_kq0 * 4 + 0) * 68 + sm_m1] = r1.x;
        A[(sm_kq0 * 4 + 1) * 68 + sm_m1] = r1.y;
        A[(sm_kq0 * 4 + 2) * 68 + sm_m1] = r1.z;
        A[(sm_kq0 * 4 + 3) * 68 + sm_m1] = r1.w;
    };

    for (int t = 0; t < OUTT; t++) {
        const int cur = t & 1;
        const float* hprev = d_hd[cur];
        float* hnext       = d_hd[cur ^ 1];
        const float* Gin = d_GinD + (size_t)t * Bb * H4v;

        float ginr[4];
#pragma unroll
        for (int r = 0; r < 4; r++) ginr[r] = __ldg(Gin + gidx4[r]);

        u64 acc[2] = {0ULL, 0ULL};
        float4 r0 = *(const float4*)(hprev + sm_m0 * 512 + sm_kq0 * 4);
        float4 r1 = *(const float4*)(hprev + sm_m1 * 512 + sm_kq0 * 4);
        stage_write(Asb, r0, r1);
        __syncthreads();

        for (int kb = 0; kb < 16; kb++) {
            if (kb + 1 < 16) {
                int k0 = (kb + 1) * 32;
                r0 = *(const float4*)(hprev + sm_m0 * 512 + k0 + sm_kq0 * 4);
                r1 = *(const float4*)(hprev + sm_m1 * 512 + k0 + sm_kq0 * 4);
            }
            const float* A = Asb + (kb & 1) * 2176;
#pragma unroll
            for (int k = 0; k < 32; k++) {
                float2 a = *(const float2*)(A + k * 68 + ty * 2);
                u64 w = *(const u64*)(WtD + (kb * 32 + k) * 20 + tx * 2);
                acc[0] = ffma2(pack2(a.x, a.x), w, acc[0]);
                acc[1] = ffma2(pack2(a.y, a.y), w, acc[1]);
            }
            if (kb + 1 < 16) stage_write(Asb + ((kb + 1) & 1) * 2176, r0, r1);
            __syncthreads();
        }
#pragma unroll
        for (int i = 0; i < 2; i++) {
            int m = ty * 2 + i;
            float lo, hi; unpack2(acc[i], lo, hi);
            int n0 = tx * 2;
            gsm[m * 17 + n0]     = lo;
            gsm[m * 17 + n0 + 1] = hi;
        }
        __syncthreads();
        {
            int b = tid >> 2, u = tid & 3;
            float gi = gsm[b * 17 + u]      + ginr[0];
            float gf = gsm[b * 17 + 4 + u]  + ginr[1];
            float gg = gsm[b * 17 + 8 + u]  + ginr[2];
            float go = gsm[b * 17 + 12 + u] + ginr[3];
            int hidx = b * Hh + hb0 + u;
            float c_old = d_cd[hidx];
            float c2 = sigf(gf) * c_old + sigf(gi) * tanhf(gg);
            float h2 = sigf(go) * tanhf(c2);
            hnext[hidx] = h2;
            d_cd[hidx] = c2;
            size_t cidx = ((size_t)t * Bb + b) * H3v + H2v + hb0 + u;
            unsigned bits = __float_as_uint(h2);
            float rr = h2 - __uint_as_float(bits & 0xFFFF0000u);
            d_ctxH[cidx] = (u16)(bits >> 16);
            d_ctxL[cidx] = (u16)(pbf2(rr, rr) & 0xFFFFu);
        }
        gridbar(&d_bcD, &d_bgD, 128);

        const float* h2p = d_hd[cur ^ 1];
        if (tid < 128) ((float4*)qs)[tid] = ((const float4*)(h2p + (size_t)ab * Hh))[tid];
        __syncthreads();
        {
            int w = tid >> 5, lane = tid & 31;
#pragma unroll
            for (int i = 0; i < 16; i++) {
                int tt = w + 8 * i;
                const float4* Ep = (const float4*)(d_E + ((size_t)tt * Bb + ab) * Hh);
                float s = 0.f;
#pragma unroll
                for (int it = 0; it < 4; it++) {
                    int h4 = it * 32 + lane;
                    float4 e4 = Ep[h4];
                    float4 q4 = ((const float4*)qs)[h4];
                    s += e4.x * q4.x + e4.y * q4.y + e4.z * q4.z + e4.w * q4.w;
                }
#pragma unroll
                for (int o = 16; o; o >>= 1) s += __shfl_xor_sync(0xffffffffu, s, o);
                if (lane == 0) es[tt] = s + d_eb[tt * Bb + ab];
            }
        }
        __syncthreads();
        float mx = -1e30f;
        for (int i = 0; i < Tt; i++) mx = fmaxf(mx, es[i]);
        if (tid < Tt) as_[tid] = expf(es[tid] - mx);
        __syncthreads();
        float sum = 0.f;
        for (int i = 0; i < Tt; i++) sum += as_[i];
        float inv = 1.f / sum;
        if (tid < 128) {
            int idx4 = half * 128 + tid;
            float4 a4 = make_float4(0.f, 0.f, 0.f, 0.f);
            for (int tt = 0; tt < Tt; tt++) {
                int L = ab * Tt + tt;
                int t0 = L >> 6, b0 = L & 63;
                float4 e4 = ((const float4*)(d_enc + ((size_t)t0 * Bb + b0) * H2v))[idx4];
                float a = as_[tt];
                a4.x += a * e4.x; a4.y += a * e4.y; a4.z += a * e4.z; a4.w += a * e4.w;
            }
            a4.x *= inv; a4.y *= inv; a4.z *= inv; a4.w *= inv;
            size_t base = ((size_t)t * Bb + ab) * H3v + (size_t)idx4 * 4;
            unsigned b0_ = __float_as_uint(a4.x), b1_ = __float_as_uint(a4.y);
            unsigned b2_ = __float_as_uint(a4.z), b3_ = __float_as_uint(a4.w);
            unsigned h01 = (b0_ >> 16) | (b1_ & 0xFFFF0000u);
            unsigned h23 = (b2_ >> 16) | (b3_ & 0xFFFF0000u);
            float r0_ = a4.x - __uint_as_float(b0_ & 0xFFFF0000u);
            float r1_ = a4.y - __uint_as_float(b1_ & 0xFFFF0000u);
            float r2_ = a4.z - __uint_as_float(b2_ & 0xFFFF0000u);
            float r3_ = a4.w - __uint_as_float(b3_ & 0xFFFF0000u);
            *(uint2*)(d_ctxH + base) = make_uint2(h01, h23);
            *(uint2*)(d_ctxL + base) = make_uint2(pbf2(r0_, r1_), pbf2(r2_, r3_));
        }
        __syncthreads();
    }
}

// ---------------- concat final encoder states ----------------
__global__ void concat_hc() {
    int i = blockIdx.x * blockDim.x + threadIdx.x;
    if (i < Bb * H2v) {
        int b = i >> 10, h = i & 1023;
        d_hcat[i] = (h < Hh) ? d_hf[0][b * Hh + h] : d_hb[0][b * Hh + h - Hh];
        d_ccat[i] = (h < Hh) ? d_cf[b * Hh + h] : d_cb[b * Hh + h - Hh];
    }
}

// ---------------- host ----------------
static void* symaddr(const void* sym) {
    void* p = nullptr;
    cudaGetSymbolAddress(&p, sym);
    return p;
}

extern "C" void kernel_launch(void* const* d_in, const int* in_sizes, int n_in,
                              void* d_out, int out_size) {
    int s = (in_sizes[3] == 1) ? 4 : 3;
    const int*   x      = (const int*)d_in[0];
    const int*   lens   = (const int*)d_in[1];
    const int*   y      = (const int*)d_in[2];
    const float* emb_in = (const float*)d_in[s + 0];
    const float* emb_out= (const float*)d_in[s + 1];
    const float* W_ih_f = (const float*)d_in[s + 2];
    const float* W_hh_f = (const float*)d_in[s + 3];
    const float* b_f    = (const float*)d_in[s + 4];
    const float* W_ih_b = (const float*)d_in[s + 5];
    const float* W_hh_b = (const float*)d_in[s + 6];
    const float* b_b    = (const float*)d_in[s + 7];
    const float* W_rh   = (const float*)d_in[s + 8];
    const float* b_rh   = (const float*)d_in[s + 9];
    const float* W_rc   = (const float*)d_in[s + 10];
    const float* b_rc   = (const float*)d_in[s + 11];
    const float* W_ih_d = (const float*)d_in[s + 12];
    const float* W_hh_d = (const float*)d_in[s + 13];
    const float* b_d    = (const float*)d_in[s + 14];
    const float* W_V    = (const float*)d_in[s + 15];
    const float* b_V    = (const float*)d_in[s + 16];
    const float* W_fc   = (const float*)d_in[s + 17];
    const float* b_fc   = (const float*)d_in[s + 18];
    float* out = (float*)d_out;

    float* ginF = (float*)symaddr(d_GinF);
    float* ginB = (float*)symaddr(d_GinB);
    float* ginD = (float*)symaddr(d_GinD);
    float* hcat = (float*)symaddr(d_hcat);
    float* ccat = (float*)symaddr(d_ccat);
    float* hd   = (float*)symaddr(d_hd);
    float* cd   = (float*)symaddr(d_cd);
    float* enc  = (float*)symaddr(d_enc);
    float* Ebuf = (float*)symaddr(d_E);
    float* WVt  = (float*)symaddr(d_WVt);
    float* zer  = (float*)symaddr(d_zero);
    u16* WfcH = (u16*)symaddr(d_WfcH);
    u16* WfcL = (u16*)symaddr(d_WfcL);
    u16* ctxH = (u16*)symaddr(d_ctxH);
    u16* ctxL = (u16*)symaddr(d_ctxL);
    int* tokF = (int*)symaddr(d_tokF);
    int* tokB = (int*)symaddr(d_tokB);
    int* tokD = (int*)symaddr(d_tokD);

    static int attr_set = 0;
    if (!attr_set) {
        cudaFuncSetAttribute(mma_gemm_kernel<true>,
                             cudaFuncAttributeMaxDynamicSharedMemorySize, MM_SMEM);
        cudaFuncSetAttribute(mma_gemm_kernel<false>,
                             cudaFuncAttributeMaxDynamicSharedMemorySize, MM_SMEM);
        cudaFuncSetAttribute(fc_bf16_kernel,
                             cudaFuncAttributeMaxDynamicSharedMemorySize, MM_SMEM);
        cudaFuncSetAttribute(lstm_enc_persist,
                             cudaFuncAttributeMaxDynamicSharedMemorySize, ENC_SMEM);
        cudaFuncSetAttribute(lstm_dec_persist,
                             cudaFuncAttributeMaxDynamicSharedMemorySize, DEC_SMEM);
        attr_set = 1;
    }

    init_prep_kernel<<<512, 256>>>(x, lens, y, W_V);

    mma_gemm_kernel<true><<<dim3(Tt * Bb / 128, H4v / 128), 256, MM_SMEM>>>(
        emb_in, tokF, W_ih_f, b_f, ginF, H4v, Ee);
    mma_gemm_kernel<true><<<dim3(Tt * Bb / 128, H4v / 128), 256, MM_SMEM>>>(
        emb_in, tokB, W_ih_b, b_b, ginB, H4v, Ee);
    mma_gemm_kernel<true><<<dim3(OUTT * Bb / 128, H4v / 128), 256, MM_SMEM>>>(
        emb_out, tokD, W_ih_d, b_d, ginD, H4v, Ee);

    // encoder: 128 HMMA LSTM blocks + 20 spare blocks converting W_fc concurrently
    lstm_enc_persist<<<148, 256, ENC_SMEM>>>(W_hh_f, W_hh_b, lens, W_fc);

    concat_hc<<<(Bb * H2v + 255) / 256, 256>>>();
    gemm_kernel<64, 32, 16, 4, 4><<<dim3(Hh / 32, 1), 128>>>(
        hcat, H2v, W_rh, b_rh, hd, Bb, Hh, H2v);
    gemm_kernel<64, 32, 16, 4, 4><<<dim3(Hh / 32, 1), 128>>>(
        ccat, H2v, W_rc, b_rc, cd, Bb, Hh, H2v);

    mma_gemm_kernel<false><<<dim3(Tt * Bb / 128, Hh / 128), 256, MM_SMEM>>>(
        enc, nullptr, WVt, zer, Ebuf, Hh, H2v);
    ebias_kernel<<<Tt * Bb / 8, 256>>>(b_V);

    lstm_dec_persist<<<128, 256, DEC_SMEM>>>(W_hh_d);

    fc_bf16_kernel<<<dim3(OUTT * Bb / 128, (Vv + 127) / 128), 256, MM_SMEM>>>(
        ctxH, ctxL, WfcH, WfcL, b_fc, out, Vv, H3v);
}